// round 14
// baseline (speedup 1.0000x reference)
#include <cuda_runtime.h>
#include <cstdint>

// Problem dims (fixed): B=16, Ci=Co=64, S=256, m1=m2=32
// ---------------- device scratch (no allocs allowed) ----------------
__device__ __align__(16) float2 g_tab[264];                       // padded cos/sin table (K45 ph1)
__device__ __align__(16) float2 g_tw1[63*32];                     // [s-1][ky] twiddles
__device__ __align__(16) float2 g_W [63*32*64*64];                // [f][ky][i][o]
__device__ __align__(16) float2 g_X2[63*32*16*64];                // [f][ky][b][i]
__device__ __align__(16) float2 g_X3[16*64*63*32];                // [b][o][f][ky]

__device__ __forceinline__ int tp(int i) { return i + (i >> 5); }

// ---------------- init: all tables ----------------
__global__ void sc_tabs() {
    int t = blockIdx.x * 256 + threadIdx.x;
    if (t < 264) {
        int k = t / 33;
        int idx = t - k;
        float ang = (float)(6.283185307179586 * (double)idx / 256.0);
        g_tab[t] = make_float2(cosf(ang), sinf(ang));
    }
    int e1 = t - 264;
    if (e1 >= 0 && e1 < 63 * 32) {
        int s = (e1 >> 5) + 1, ky = e1 & 31;           // s = 1..63
        double ang = 6.283185307179586 * (double)((ky * s) % 256) / 256.0;
        g_tw1[e1] = make_float2((float)cos(ang), (float)sin(ang));
    }
}

// ---------------- build W: ky=0 plane ----------------
__global__ void sc_build_w0(const float* __restrict__ y0r, const float* __restrict__ y0i,
                            const float* __restrict__ w00) {
    int t = blockIdx.x * 256 + threadIdx.x;
    if (t >= 63 * 4096) return;
    int io = t & 4095;
    int f  = t >> 12;
    float wr, wi;
    if (f < 31)       { wr = y0r[io * 31 + f];        wi = y0i[io * 31 + f]; }
    else if (f == 31) { wr = w00[io];                 wi = 0.f; }
    else              { wr = y0r[io * 31 + (62 - f)]; wi = -y0i[io * 31 + (62 - f)]; }
    g_W[(size_t)(f * 32) * 4096 + io] = make_float2(wr, wi);
}

// ---------------- build W: ky>=1 planes via tiled transpose ----------------
__global__ void sc_build_wt(const float* __restrict__ ypr, const float* __restrict__ ypi) {
    __shared__ float2 tile[32][33];
    int tx = threadIdx.x, ty = threadIdx.y;        // 32 x 8
    int fk0 = blockIdx.x * 32, io0 = blockIdx.y * 32;
#pragma unroll
    for (int k = 0; k < 4; k++) {
        int io = io0 + ty + 8 * k;
        int fk = fk0 + tx;
        if (fk < 1953)
            tile[ty + 8 * k][tx] = make_float2(ypr[(size_t)io * 1953 + fk],
                                               ypi[(size_t)io * 1953 + fk]);
    }
    __syncthreads();
#pragma unroll
    for (int k = 0; k < 4; k++) {
        int fk = fk0 + ty + 8 * k;
        if (fk < 1953) {
            int f  = fk / 31;
            int ky = fk - f * 31 + 1;
            g_W[(size_t)(f * 32 + ky) * 4096 + io0 + tx] = tile[tx][ty + 8 * k];
        }
    }
}

// ---------------- K12: fused DFT-y + DFT-x per (b,i) image (round-8 version) ----------
#define SMEM12 ((4*64*130 + 256*4) * 4 + 256*32*8)
__global__ __launch_bounds__(512, 1) void sc_k12(const float* __restrict__ x) {
    extern __shared__ float sm12[];
    float* sEp = sm12;                    // [s(0..63)][slot(130 pad, 128 used)]
    float* sEm = sEp + 64 * 130;
    float* sOp = sEm + 64 * 130;
    float* sOm = sOp + 64 * 130;
    float* sbase = sOm + 64 * 130;        // [row(256)][4]
    float2* sX1 = (float2*)(sbase + 1024);// [x(256)][ky(32)]
    int tid = threadIdx.x, bid = blockIdx.x;      // bid = b*64 + i
    int lane = tid & 31, w = tid >> 5;            // w = 0..15
    const float* gx = x + (size_t)bid * 65536;
    int sp = (32 - lane) & 31;

    // ---- phase 1: DFT along y, warp-local ----
    int ky0 = lane & 7, rp2 = lane >> 3;
    int slot0 = 8 * w + 2 * rp2;
    int p1q = ky0 & 1;
    float sgn1 = p1q ? -1.f : 1.f;
    int m41 = ky0 & 3;
    float c64a = (m41 == 0) ? 1.f : (m41 == 2 ? -1.f : 0.f);
    float s64a = (m41 == 1) ? 1.f : (m41 == 3 ? -1.f : 0.f);
    const float* EE = p1q ? sEm : sEp;
    const float* OO = p1q ? sOp : sOm;
    float Kk[4], t1x[4], t1y[4];
#pragma unroll
    for (int j = 0; j < 4; j++) {
        float2 t1 = __ldg(&g_tw1[ky0 + 8 * j]);
        Kk[j] = 2.f * t1.x;  t1x[j] = t1.x;  t1y[j] = t1.y;
    }

    for (int it = 0; it < 2; it++) {
        int rowbase = 8 * w + 128 * it;
#pragma unroll
        for (int r = 0; r < 8; r++) {
            int row = rowbase + r;
            int slot = 8 * w + r;
            const float* rp = gx + row * 256;
            float v[8];
#pragma unroll
            for (int k = 0; k < 8; k++) v[k] = rp[lane + 32 * k];
            float E1[4], O1[4];
#pragma unroll
            for (int k = 0; k < 4; k++) {
                float p1 = __shfl_sync(0xFFFFFFFFu, v[7 - k], sp);
                if (lane == 0) p1 = v[(8 - k) & 7];
                E1[k] = v[k] + p1;
                O1[k] = v[k] - p1;
            }
#pragma unroll
            for (int k = 0; k < 2; k++) {
                int c = lane + 32 * k;
                float qe = __shfl_sync(0xFFFFFFFFu, E1[3 - k], sp);
                float qo = __shfl_sync(0xFFFFFFFFu, O1[3 - k], sp);
                if (k == 1 && lane == 0) { qe = E1[3]; qo = O1[3]; }
                float ep = E1[k] + qe, em = E1[k] - qe;
                float op = O1[k] + qo, om = O1[k] - qo;
                if (c >= 1 && c <= 63) {
                    sEp[c * 130 + slot] = ep;
                    sEm[c * 130 + slot] = em;
                    sOp[c * 130 + slot] = op;
                    sOm[c * 130 + slot] = om;
                }
            }
            if (lane == 0) {
                sbase[row * 4 + 0] = v[0];
                sbase[row * 4 + 1] = v[4];
                sbase[row * 4 + 2] = v[2] + v[6];
                sbase[row * 4 + 3] = v[2] - v[6];
            }
        }
        __syncwarp();

        int row0 = slot0 + 128 * it;
        float cp[4], cc[4], zp[4], zc[4];
#pragma unroll
        for (int j = 0; j < 4; j++) {
            cp[j] = 1.f;  cc[j] = t1x[j];
            zp[j] = 0.f;  zc[j] = t1y[j];
        }
        float re[4][2], im[4][2];
        {
            const float* b0 = sbase + row0 * 4;
            const float* b1 = sbase + (row0 + 1) * 4;
            float base0 = b0[0] + sgn1 * b0[1] + c64a * b0[2];
            float base1 = b1[0] + sgn1 * b1[1] + c64a * b1[2];
            float imb0 = -s64a * b0[3];
            float imb1 = -s64a * b1[3];
#pragma unroll
            for (int j = 0; j < 4; j++) {
                re[j][0] = base0;  re[j][1] = base1;
                im[j][0] = imb0;   im[j][1] = imb1;
            }
        }
#pragma unroll 7
        for (int s = 1; s < 64; s++) {
            float2 e = *(const float2*)(EE + s * 130 + slot0);
            float2 o = *(const float2*)(OO + s * 130 + slot0);
#pragma unroll
            for (int j = 0; j < 4; j++) {
                re[j][0] += e.x * cc[j];  im[j][0] -= o.x * zc[j];
                re[j][1] += e.y * cc[j];  im[j][1] -= o.y * zc[j];
                float cn = Kk[j] * cc[j] - cp[j];  cp[j] = cc[j];  cc[j] = cn;
                float zn = Kk[j] * zc[j] - zp[j];  zp[j] = zc[j];  zc[j] = zn;
            }
        }
        const float SC = 1.f / 256.f;
#pragma unroll
        for (int j = 0; j < 4; j++) {
            int ky = ky0 + 8 * j;
#pragma unroll
            for (int r = 0; r < 2; r++)
                sX1[(row0 + r) * 32 + ky] = make_float2(re[j][r] * SC, im[j][r] * SC);
        }
        __syncwarp();
    }
    __syncthreads();

    // ---- phase 2: 4x fold in x (in place) ----
    for (int e = tid; e < 63 * 32; e += 512) {
        int xx = (e >> 5) + 1, ky = e & 31;
        float2 a = sX1[xx * 32 + ky];
        float2 b = sX1[(256 - xx) * 32 + ky];
        float2 c = sX1[(128 - xx) * 32 + ky];
        float2 d = sX1[(128 + xx) * 32 + ky];
        sX1[xx * 32 + ky]         = make_float2(a.x + b.x + c.x + d.x, a.y + b.y + c.y + d.y);
        sX1[(256 - xx) * 32 + ky] = make_float2(a.x + b.x - c.x - d.x, a.y + b.y - c.y - d.y);
        sX1[(128 - xx) * 32 + ky] = make_float2(a.x - b.x + c.x - d.x, a.y - b.y + c.y - d.y);
        sX1[(128 + xx) * 32 + ky] = make_float2(a.x - b.x - c.x + d.x, a.y - b.y - c.y + d.y);
    }
    __syncthreads();

    // ---- phase 2: DFT along x (63 terms), 2 freqs per thread ----
    int ky = tid & 31, g = tid >> 5;          // g = 0..15, freqs {g, g+16}
    int bi = bid;
    int p = g & 1;
    float Cr0=0,Ci0=0,Sr0=0,Si0=0, Cr1=0,Ci1=0,Sr1=0,Si1=0;
#pragma unroll 7
    for (int xx = 1; xx < 64; xx++) {
        int eeIdx = (p ? (256 - xx) : xx) * 32 + ky;
        int ooIdx = (p ? (128 - xx) : (128 + xx)) * 32 + ky;
        float2 e = sX1[eeIdx];
        float2 o = sX1[ooIdx];
        const float2* twr = &g_tw1[(xx - 1) * 32];
        float2 t0 = __ldg(twr + g);
        float2 t1 = __ldg(twr + g + 16);
        Cr0 += e.x*t0.x; Ci0 += e.y*t0.x; Sr0 += o.x*t0.y; Si0 += o.y*t0.y;
        Cr1 += e.x*t1.x; Ci1 += e.y*t1.x; Sr1 += o.x*t1.y; Si1 += o.y*t1.y;
    }
    float2 b0   = sX1[0 * 32 + ky];
    float2 b128 = sX1[128 * 32 + ky];
    float2 x64  = sX1[64 * 32 + ky];
    float2 x192 = sX1[192 * 32 + ky];
    float sgnB = p ? -1.f : 1.f;
    float baseR = b0.x + sgnB * b128.x, baseI = b0.y + sgnB * b128.y;
    float E64r = x64.x + x192.x, E64i = x64.y + x192.y;
    float O64r = x64.x - x192.x, O64i = x64.y - x192.y;
    float tpR, tpI, tmR, tmI;
    int gm4 = g & 3;
    if (!p) {
        float c4 = (gm4 == 0) ? 1.f : -1.f;
        tpR = tmR = c4 * E64r;  tpI = tmI = c4 * E64i;
    } else {
        float s4 = (gm4 == 1) ? 1.f : -1.f;
        tpR = s4 * O64i;  tpI = -s4 * O64r;
        tmR = -s4 * O64i; tmI = s4 * O64r;
    }
#define K2OUT(FQ, CR, CI, SR, SI)                                                        \
    g_X2[(size_t)((31 + (FQ)) * 32 + ky) * 1024 + bi] =                                  \
        make_float2(baseR + tpR + (CR) + (SI), baseI + tpI + (CI) - (SR));               \
    if ((FQ) > 0)                                                                        \
        g_X2[(size_t)((31 - (FQ)) * 32 + ky) * 1024 + bi] =                              \
            make_float2(baseR + tmR + (CR) - (SI), baseI + tmI + (CI) + (SR));
    K2OUT(g,      Cr0, Ci0, Sr0, Si0)
    K2OUT(g + 16, Cr1, Ci1, Sr1, Si1)
#undef K2OUT
}

// ---------------- K3: channel mix, 4 (f,ky) tiles/block, 4b x 4o register blocking ----
__global__ __launch_bounds__(256, 4) void sc_k3() {
    __shared__ __align__(16) float2 sX[4 * 1024];
    int tid = threadIdx.x, bid = blockIdx.x;
    int tile = tid >> 6, t = tid & 63;
    int og = t & 15, bg = t >> 4;
    int fk = bid * 4 + tile;
    {
        float4* dst = (float4*)sX;
        for (int q = tid; q < 2048; q += 256) {
            int tq = q >> 9;
            dst[q] = *(const float4*)(g_X2 + (size_t)(bid * 4 + tq) * 1024 + (q & 511) * 2);
        }
    }
    __syncthreads();

    float ar[4][4], ai[4][4];
#pragma unroll
    for (int bb = 0; bb < 4; bb++)
#pragma unroll
        for (int oo = 0; oo < 4; oo++) { ar[bb][oo] = 0.f; ai[bb][oo] = 0.f; }

    const float2* Wbase = g_W + (size_t)fk * 4096 + og * 4;
    const float2* Xbase = sX + tile * 1024 + bg * 4 * 64;
#pragma unroll 4
    for (int i = 0; i < 64; i++) {
        float4 w01 = __ldg((const float4*)(Wbase + i * 64));
        float4 w23 = __ldg((const float4*)(Wbase + i * 64 + 2));
        float2 v0 = Xbase[i];
        float2 v1 = Xbase[64 + i];
        float2 v2 = Xbase[128 + i];
        float2 v3 = Xbase[192 + i];
#define CMAC(BB, V)                                                          \
        ar[BB][0] += V.x*w01.x - V.y*w01.y;  ai[BB][0] += V.x*w01.y + V.y*w01.x; \
        ar[BB][1] += V.x*w01.z - V.y*w01.w;  ai[BB][1] += V.x*w01.w + V.y*w01.z; \
        ar[BB][2] += V.x*w23.x - V.y*w23.y;  ai[BB][2] += V.x*w23.y + V.y*w23.x; \
        ar[BB][3] += V.x*w23.z - V.y*w23.w;  ai[BB][3] += V.x*w23.w + V.y*w23.z;
        CMAC(0, v0) CMAC(1, v1) CMAC(2, v2) CMAC(3, v3)
#undef CMAC
    }
    __syncthreads();
#pragma unroll
    for (int bb = 0; bb < 4; bb++)
#pragma unroll
        for (int oo = 0; oo < 4; oo++) {
            int bo = (bg * 4 + bb) * 64 + og * 4 + oo;
            sX[bo * 4 + tile] = make_float2(ar[bb][oo], ai[bb][oo]);
        }
    __syncthreads();
    int fk0 = bid * 4;
    for (int q = tid; q < 2048; q += 256) {
        int bo = q >> 1, half = q & 1;
        float4 val = *(const float4*)(sX + bo * 4 + half * 2);
        *(float4*)(g_X3 + (size_t)bo * 2016 + fk0 + half * 2) = val;
    }
}

// ---------------- K45: fused iDFT-x + irfft-y per (b,o), 512 threads ----------------
// Phase 1: 64 xs-slots x 2 xi iterations. Phase 2: 16 warps, 8 rows/thread x 2 iters.
// Total load/FFMA counts identical to the 256-thread version; occupancy doubled.
#define SMEM45 ((8192 + 2016 + 992 + 992 + 264) * 8)
__global__ __launch_bounds__(512, 2) void sc_k45(float* __restrict__ out) {
    extern __shared__ float smf[];
    float2* sYt  = (float2*)smf;            // [x(256)][ky(32)]
    float2* sX3  = sYt + 8192;              // 2016
    float2* sU   = sX3 + 2016;              // 992
    float2* sV   = sU + 992;                // 992
    float2* stab = sV + 992;                // 264
    int tid = threadIdx.x, bid = blockIdx.x;            // bid = b*64+o

    // ---- phase 1: iDFT along x -> sYt ----
    {
        const float4* src = (const float4*)(g_X3 + (size_t)bid * 2016);
        float4* dst = (float4*)sX3;
        for (int q = tid; q < 1008; q += 512) dst[q] = src[q];
        for (int q = tid; q < 264; q += 512) stab[q] = g_tab[q];
    }
    __syncthreads();
    for (int e = tid; e < 992; e += 512) {
        int ky = e & 31, fq = (e >> 5) + 1;
        float2 P = sX3[(31 + fq) * 32 + ky];
        float2 Q = sX3[(31 - fq) * 32 + ky];
        sU[e] = make_float2(P.x + Q.x, P.y + Q.y);
        sV[e] = make_float2(-(P.y - Q.y), P.x - Q.x);   // i*(P-Q)
    }
    __syncthreads();

    {
        int ky4 = (tid & 7) * 4, xs = tid >> 3;          // xs = 0..63
        const float4* m = (const float4*)(sX3 + 31 * 32 + ky4);
        float4 m01 = m[0], m23 = m[1];
        for (int xi = 0; xi < 2; xi++) {
            int xx = xs + 64 * xi;                       // 0..127
            float c0 = m01.x, c1 = m01.y, c2 = m01.z, c3 = m01.w;
            float c4 = m23.x, c5 = m23.y, c6 = m23.z, c7 = m23.w;
            float s0 = 0, s1 = 0, s2 = 0, s3 = 0, s4 = 0, s5 = 0, s6 = 0, s7 = 0;
            int p = 0;
#pragma unroll 4
            for (int fq = 1; fq < 32; fq++) {
                p = (p + xx) & 255;
                float2 t = stab[tp(p)];
                const float4* up = (const float4*)(sU + (fq - 1) * 32 + ky4);
                const float4* vp = (const float4*)(sV + (fq - 1) * 32 + ky4);
                float4 u01 = up[0], u23 = up[1], v01 = vp[0], v23 = vp[1];
                c0 += t.x * u01.x;  s0 += t.y * v01.x;
                c1 += t.x * u01.y;  s1 += t.y * v01.y;
                c2 += t.x * u01.z;  s2 += t.y * v01.z;
                c3 += t.x * u01.w;  s3 += t.y * v01.w;
                c4 += t.x * u23.x;  s4 += t.y * v23.x;
                c5 += t.x * u23.y;  s5 += t.y * v23.y;
                c6 += t.x * u23.z;  s6 += t.y * v23.z;
                c7 += t.x * u23.w;  s7 += t.y * v23.w;
            }
            float4* o1 = (float4*)(sYt + xx * 32 + ky4);
            o1[0] = make_float4(c0 + s0, c1 + s1, c2 + s2, c3 + s3);
            o1[1] = make_float4(c4 + s4, c5 + s5, c6 + s6, c7 + s7);
            if (xx > 0) {
                float4* o2 = (float4*)(sYt + (256 - xx) * 32 + ky4);
                o2[0] = make_float4(c0 - s0, c1 - s1, c2 - s2, c3 - s3);
                o2[1] = make_float4(c4 - s4, c5 - s5, c6 - s6, c7 - s7);
            }
        }
        if (tid < 32) {
            int ky = tid;
            float2 acc = sX3[31 * 32 + ky];
#pragma unroll 4
            for (int fq = 1; fq < 32; fq++) {
                float2 u = sU[(fq - 1) * 32 + ky];
                float sg = (fq & 1) ? -1.f : 1.f;
                acc.x += sg * u.x;  acc.y += sg * u.y;
            }
            sYt[128 * 32 + ky] = acc;
        }
    }
    __syncthreads();

    // ---- phase 2: irfft along y, 8 rows/thread, 2 outer iterations (16 warps) ----
    int l = tid & 31, w = tid >> 5;                     // w = 0..15
    float2 tA = __ldg(&g_tw1[l]);
    const float R45 = 0.70710678118654752f;
    float cB1 = (tA.x - tA.y) * R45;
    float sB1 = (tA.x + tA.y) * R45;
    float KA = 2.f * tA.x, KB = 2.f * cB1;
    const float SC1 = 1.f / 256.f, SC2 = 2.f / 256.f;

    for (int rgh = 0; rgh < 2; rgh++) {
        const float2* sY = sYt + (rgh * 128 + w * 8) * 32;   // 8 rows for this thread
        float cAc = 1.f, cAp = tA.x;
        float zAc = 0.f, zAp = -tA.y;
        float cBc = 1.f, cBp = cB1;
        float zBc = 0.f, zBp = -sB1;

        float Ae0[8]={0,0,0,0,0,0,0,0}, Se0[8]={0,0,0,0,0,0,0,0};
        float Ao0[8]={0,0,0,0,0,0,0,0}, So0[8]={0,0,0,0,0,0,0,0};
        float Ae1[8]={0,0,0,0,0,0,0,0}, Se1[8]={0,0,0,0,0,0,0,0};
        float Ao1[8]={0,0,0,0,0,0,0,0}, So1[8]={0,0,0,0,0,0,0,0};

#pragma unroll 4
        for (int kp = 0; kp < 16; kp++) {
            float n;
            n = KA * cAc - cAp;  cAp = cAc;  cAc = n;
            n = KA * zAc - zAp;  zAp = zAc;  zAc = n;
            n = KB * cBc - cBp;  cBp = cBc;  cBc = n;
            n = KB * zBc - zBp;  zBp = zBc;  zBc = n;
            int kyo = 2 * kp + 1;
#pragma unroll
            for (int r = 0; r < 8; r++) {
                float2 v = sY[r * 32 + kyo];
                Ao0[r] += v.x * cAc;  So0[r] += v.y * zAc;
                Ao1[r] += v.x * cBc;  So1[r] += v.y * zBc;
            }
            if (kp < 15) {
                n = KA * cAc - cAp;  cAp = cAc;  cAc = n;
                n = KA * zAc - zAp;  zAp = zAc;  zAc = n;
                n = KB * cBc - cBp;  cBp = cBc;  cBc = n;
                n = KB * zBc - zBp;  zBp = zBc;  zBc = n;
                int kye = 2 * kp + 2;
#pragma unroll
                for (int r = 0; r < 8; r++) {
                    float2 v = sY[r * 32 + kye];
                    Ae0[r] += v.x * cAc;  Se0[r] += v.y * zAc;
                    Ae1[r] += v.x * cBc;  Se1[r] += v.y * zBc;
                }
            }
        }

#pragma unroll
        for (int r = 0; r < 8; r++) {
            size_t ob = ((size_t)bid * 256 + rgh * 128 + w * 8 + r) * 256;
            float bx = sY[r * 32].x * SC1;
            float a  = SC2 * (Ae0[r] + Ao0[r]) + bx;
            float s  = SC2 * (Se0[r] + So0[r]);
            float am = SC2 * (Ae0[r] - Ao0[r]) + bx;
            float sm = SC2 * (Se0[r] - So0[r]);
            out[ob + l]       = a - s;
            out[ob + 128 - l] = am + sm;
            if (l > 0) {
                out[ob + 256 - l] = a + s;
                out[ob + 128 + l] = am - sm;
            }
            float a1  = SC2 * (Ae1[r] + Ao1[r]) + bx;
            float s1  = SC2 * (Se1[r] + So1[r]);
            float am1 = SC2 * (Ae1[r] - Ao1[r]) + bx;
            float sm1 = SC2 * (Se1[r] - So1[r]);
            out[ob + 32 + l]  = a1 - s1;
            out[ob + 224 - l] = a1 + s1;
            out[ob + 96 - l]  = am1 + sm1;
            out[ob + 160 + l] = am1 - sm1;
        }
        // tail t = 64 / 192 for these 8 rows
        {
            int ky = l;
            float sc = (ky == 0) ? SC1 : SC2;
            int m4 = ky & 3;
            float c64 = (m4 == 0) ? sc : (m4 == 2 ? -sc : 0.f);
            float s64 = (m4 == 1) ? sc : (m4 == 3 ? -sc : 0.f);
#pragma unroll
            for (int r = 0; r < 8; r++) {
                float2 v = sY[r * 32 + ky];
                float p = v.x * c64 - v.y * s64;
                float q = v.x * c64 + v.y * s64;
#pragma unroll
                for (int off = 16; off; off >>= 1) {
                    p += __shfl_xor_sync(0xFFFFFFFFu, p, off);
                    q += __shfl_xor_sync(0xFFFFFFFFu, q, off);
                }
                if (l == 0) {
                    size_t ob = ((size_t)bid * 256 + rgh * 128 + w * 8 + r) * 256;
                    out[ob + 64]  = p;
                    out[ob + 192] = q;
                }
            }
        }
    }
}

// ---------------- launch: fork W-build onto a side stream, overlap with K12 ----------
extern "C" void kernel_launch(void* const* d_in, const int* in_sizes, int n_in,
                              void* d_out, int out_size) {
    const float* x   = (const float*)d_in[0];
    const float* y0r = (const float*)d_in[1];
    const float* y0i = (const float*)d_in[2];
    const float* ypr = (const float*)d_in[3];
    const float* ypi = (const float*)d_in[4];
    const float* w00 = (const float*)d_in[5];
    float* out = (float*)d_out;

    cudaFuncSetAttribute(sc_k12, cudaFuncAttributeMaxDynamicSharedMemorySize, SMEM12);
    cudaFuncSetAttribute(sc_k45, cudaFuncAttributeMaxDynamicSharedMemorySize, SMEM45);

    cudaStream_t s2;
    cudaEvent_t evF, evJ;
    cudaStreamCreateWithFlags(&s2, cudaStreamNonBlocking);
    cudaEventCreateWithFlags(&evF, cudaEventDisableTiming);
    cudaEventCreateWithFlags(&evJ, cudaEventDisableTiming);

    // fork: side stream joins the capture graph at the root
    cudaEventRecord(evF, 0);
    cudaStreamWaitEvent(s2, evF, 0);

    // side stream: W build (feeds only K3)
    sc_build_w0<<<(63 * 4096 + 255) / 256, 256, 0, s2>>>(y0r, y0i, w00);
    sc_build_wt<<<dim3(62, 128), dim3(32, 8), 0, s2>>>(ypr, ypi);
    cudaEventRecord(evJ, s2);

    // main stream: tables -> K12
    sc_tabs<<<9, 256>>>();
    sc_k12<<<1024, 512, SMEM12>>>(x);

    // join before K3 (needs g_W and g_X2)
    cudaStreamWaitEvent(0, evJ, 0);
    sc_k3<<<504, 256>>>();
    sc_k45<<<1024, 512, SMEM45>>>(out);
}

// round 15
// speedup vs baseline: 1.6551x; 1.6551x over previous
#include <cuda_runtime.h>
#include <cstdint>

// Problem dims (fixed): B=16, Ci=Co=64, S=256, m1=m2=32
// ---------------- device scratch (no allocs allowed) ----------------
__device__ __align__(16) float2 g_tab[264];                       // padded cos/sin table (K45 ph1)
__device__ __align__(16) float2 g_tw1[63*32];                     // [s-1][ky] twiddles
__device__ __align__(16) float2 g_W [63*32*64*64];                // [f][ky][i][o]
__device__ __align__(16) float2 g_X2[16*64*2016];                 // [bi][fk]  (fk = f*32+ky)
__device__ __align__(16) float2 g_X3[16*64*63*32];                // [b][o][f][ky]

__device__ __forceinline__ int tp(int i) { return i + (i >> 5); }

// ---------------- init: all tables ----------------
__global__ void sc_tabs() {
    int t = blockIdx.x * 256 + threadIdx.x;
    if (t < 264) {
        int k = t / 33;
        int idx = t - k;
        float ang = (float)(6.283185307179586 * (double)idx / 256.0);
        g_tab[t] = make_float2(cosf(ang), sinf(ang));
    }
    int e1 = t - 264;
    if (e1 >= 0 && e1 < 63 * 32) {
        int s = (e1 >> 5) + 1, ky = e1 & 31;           // s = 1..63
        double ang = 6.283185307179586 * (double)((ky * s) % 256) / 256.0;
        g_tw1[e1] = make_float2((float)cos(ang), (float)sin(ang));
    }
}

// ---------------- build W: ky=0 plane ----------------
__global__ void sc_build_w0(const float* __restrict__ y0r, const float* __restrict__ y0i,
                            const float* __restrict__ w00) {
    int t = blockIdx.x * 256 + threadIdx.x;
    if (t >= 63 * 4096) return;
    int io = t & 4095;
    int f  = t >> 12;
    float wr, wi;
    if (f < 31)       { wr = y0r[io * 31 + f];        wi = y0i[io * 31 + f]; }
    else if (f == 31) { wr = w00[io];                 wi = 0.f; }
    else              { wr = y0r[io * 31 + (62 - f)]; wi = -y0i[io * 31 + (62 - f)]; }
    g_W[(size_t)(f * 32) * 4096 + io] = make_float2(wr, wi);
}

// ---------------- build W: ky>=1 planes via tiled transpose ----------------
__global__ void sc_build_wt(const float* __restrict__ ypr, const float* __restrict__ ypi) {
    __shared__ float2 tile[32][33];
    int tx = threadIdx.x, ty = threadIdx.y;        // 32 x 8
    int fk0 = blockIdx.x * 32, io0 = blockIdx.y * 32;
#pragma unroll
    for (int k = 0; k < 4; k++) {
        int io = io0 + ty + 8 * k;
        int fk = fk0 + tx;
        if (fk < 1953)
            tile[ty + 8 * k][tx] = make_float2(ypr[(size_t)io * 1953 + fk],
                                               ypi[(size_t)io * 1953 + fk]);
    }
    __syncthreads();
#pragma unroll
    for (int k = 0; k < 4; k++) {
        int fk = fk0 + ty + 8 * k;
        if (fk < 1953) {
            int f  = fk / 31;
            int ky = fk - f * 31 + 1;
            g_W[(size_t)(f * 32 + ky) * 4096 + io0 + tx] = tile[tx][ty + 8 * k];
        }
    }
}

// ---------------- K12: fused DFT-y + DFT-x per (b,i) image (round-8 version) ----------
// X2 stores are now [bi][fk]-coalesced.
#define SMEM12 ((4*64*130 + 256*4) * 4 + 256*32*8)
__global__ __launch_bounds__(512, 1) void sc_k12(const float* __restrict__ x) {
    extern __shared__ float sm12[];
    float* sEp = sm12;                    // [s(0..63)][slot(130 pad, 128 used)]
    float* sEm = sEp + 64 * 130;
    float* sOp = sEm + 64 * 130;
    float* sOm = sOp + 64 * 130;
    float* sbase = sOm + 64 * 130;        // [row(256)][4]
    float2* sX1 = (float2*)(sbase + 1024);// [x(256)][ky(32)]
    int tid = threadIdx.x, bid = blockIdx.x;      // bid = b*64 + i
    int lane = tid & 31, w = tid >> 5;            // w = 0..15
    const float* gx = x + (size_t)bid * 65536;
    int sp = (32 - lane) & 31;

    // ---- phase 1: DFT along y, warp-local ----
    int ky0 = lane & 7, rp2 = lane >> 3;
    int slot0 = 8 * w + 2 * rp2;
    int p1q = ky0 & 1;
    float sgn1 = p1q ? -1.f : 1.f;
    int m41 = ky0 & 3;
    float c64a = (m41 == 0) ? 1.f : (m41 == 2 ? -1.f : 0.f);
    float s64a = (m41 == 1) ? 1.f : (m41 == 3 ? -1.f : 0.f);
    const float* EE = p1q ? sEm : sEp;
    const float* OO = p1q ? sOp : sOm;
    float Kk[4], t1x[4], t1y[4];
#pragma unroll
    for (int j = 0; j < 4; j++) {
        float2 t1 = __ldg(&g_tw1[ky0 + 8 * j]);
        Kk[j] = 2.f * t1.x;  t1x[j] = t1.x;  t1y[j] = t1.y;
    }

    for (int it = 0; it < 2; it++) {
        int rowbase = 8 * w + 128 * it;
#pragma unroll
        for (int r = 0; r < 8; r++) {
            int row = rowbase + r;
            int slot = 8 * w + r;
            const float* rp = gx + row * 256;
            float v[8];
#pragma unroll
            for (int k = 0; k < 8; k++) v[k] = rp[lane + 32 * k];
            float E1[4], O1[4];
#pragma unroll
            for (int k = 0; k < 4; k++) {
                float p1 = __shfl_sync(0xFFFFFFFFu, v[7 - k], sp);
                if (lane == 0) p1 = v[(8 - k) & 7];
                E1[k] = v[k] + p1;
                O1[k] = v[k] - p1;
            }
#pragma unroll
            for (int k = 0; k < 2; k++) {
                int c = lane + 32 * k;
                float qe = __shfl_sync(0xFFFFFFFFu, E1[3 - k], sp);
                float qo = __shfl_sync(0xFFFFFFFFu, O1[3 - k], sp);
                if (k == 1 && lane == 0) { qe = E1[3]; qo = O1[3]; }
                float ep = E1[k] + qe, em = E1[k] - qe;
                float op = O1[k] + qo, om = O1[k] - qo;
                if (c >= 1 && c <= 63) {
                    sEp[c * 130 + slot] = ep;
                    sEm[c * 130 + slot] = em;
                    sOp[c * 130 + slot] = op;
                    sOm[c * 130 + slot] = om;
                }
            }
            if (lane == 0) {
                sbase[row * 4 + 0] = v[0];
                sbase[row * 4 + 1] = v[4];
                sbase[row * 4 + 2] = v[2] + v[6];
                sbase[row * 4 + 3] = v[2] - v[6];
            }
        }
        __syncwarp();

        int row0 = slot0 + 128 * it;
        float cp[4], cc[4], zp[4], zc[4];
#pragma unroll
        for (int j = 0; j < 4; j++) {
            cp[j] = 1.f;  cc[j] = t1x[j];
            zp[j] = 0.f;  zc[j] = t1y[j];
        }
        float re[4][2], im[4][2];
        {
            const float* b0 = sbase + row0 * 4;
            const float* b1 = sbase + (row0 + 1) * 4;
            float base0 = b0[0] + sgn1 * b0[1] + c64a * b0[2];
            float base1 = b1[0] + sgn1 * b1[1] + c64a * b1[2];
            float imb0 = -s64a * b0[3];
            float imb1 = -s64a * b1[3];
#pragma unroll
            for (int j = 0; j < 4; j++) {
                re[j][0] = base0;  re[j][1] = base1;
                im[j][0] = imb0;   im[j][1] = imb1;
            }
        }
#pragma unroll 7
        for (int s = 1; s < 64; s++) {
            float2 e = *(const float2*)(EE + s * 130 + slot0);
            float2 o = *(const float2*)(OO + s * 130 + slot0);
#pragma unroll
            for (int j = 0; j < 4; j++) {
                re[j][0] += e.x * cc[j];  im[j][0] -= o.x * zc[j];
                re[j][1] += e.y * cc[j];  im[j][1] -= o.y * zc[j];
                float cn = Kk[j] * cc[j] - cp[j];  cp[j] = cc[j];  cc[j] = cn;
                float zn = Kk[j] * zc[j] - zp[j];  zp[j] = zc[j];  zc[j] = zn;
            }
        }
        const float SC = 1.f / 256.f;
#pragma unroll
        for (int j = 0; j < 4; j++) {
            int ky = ky0 + 8 * j;
#pragma unroll
            for (int r = 0; r < 2; r++)
                sX1[(row0 + r) * 32 + ky] = make_float2(re[j][r] * SC, im[j][r] * SC);
        }
        __syncwarp();
    }
    __syncthreads();

    // ---- phase 2: 4x fold in x (in place) ----
    for (int e = tid; e < 63 * 32; e += 512) {
        int xx = (e >> 5) + 1, ky = e & 31;
        float2 a = sX1[xx * 32 + ky];
        float2 b = sX1[(256 - xx) * 32 + ky];
        float2 c = sX1[(128 - xx) * 32 + ky];
        float2 d = sX1[(128 + xx) * 32 + ky];
        sX1[xx * 32 + ky]         = make_float2(a.x + b.x + c.x + d.x, a.y + b.y + c.y + d.y);
        sX1[(256 - xx) * 32 + ky] = make_float2(a.x + b.x - c.x - d.x, a.y + b.y - c.y - d.y);
        sX1[(128 - xx) * 32 + ky] = make_float2(a.x - b.x + c.x - d.x, a.y - b.y + c.y - d.y);
        sX1[(128 + xx) * 32 + ky] = make_float2(a.x - b.x - c.x + d.x, a.y - b.y - c.y + d.y);
    }
    __syncthreads();

    // ---- phase 2: DFT along x (63 terms), 2 freqs per thread ----
    int ky = tid & 31, g = tid >> 5;          // g = 0..15, freqs {g, g+16}
    size_t obase = (size_t)bid * 2016;        // [bi][fk] layout
    int p = g & 1;
    float Cr0=0,Ci0=0,Sr0=0,Si0=0, Cr1=0,Ci1=0,Sr1=0,Si1=0;
#pragma unroll 7
    for (int xx = 1; xx < 64; xx++) {
        int eeIdx = (p ? (256 - xx) : xx) * 32 + ky;
        int ooIdx = (p ? (128 - xx) : (128 + xx)) * 32 + ky;
        float2 e = sX1[eeIdx];
        float2 o = sX1[ooIdx];
        const float2* twr = &g_tw1[(xx - 1) * 32];
        float2 t0 = __ldg(twr + g);
        float2 t1 = __ldg(twr + g + 16);
        Cr0 += e.x*t0.x; Ci0 += e.y*t0.x; Sr0 += o.x*t0.y; Si0 += o.y*t0.y;
        Cr1 += e.x*t1.x; Ci1 += e.y*t1.x; Sr1 += o.x*t1.y; Si1 += o.y*t1.y;
    }
    float2 b0   = sX1[0 * 32 + ky];
    float2 b128 = sX1[128 * 32 + ky];
    float2 x64  = sX1[64 * 32 + ky];
    float2 x192 = sX1[192 * 32 + ky];
    float sgnB = p ? -1.f : 1.f;
    float baseR = b0.x + sgnB * b128.x, baseI = b0.y + sgnB * b128.y;
    float E64r = x64.x + x192.x, E64i = x64.y + x192.y;
    float O64r = x64.x - x192.x, O64i = x64.y - x192.y;
    float tpR, tpI, tmR, tmI;
    int gm4 = g & 3;
    if (!p) {
        float c4 = (gm4 == 0) ? 1.f : -1.f;
        tpR = tmR = c4 * E64r;  tpI = tmI = c4 * E64i;
    } else {
        float s4 = (gm4 == 1) ? 1.f : -1.f;
        tpR = s4 * O64i;  tpI = -s4 * O64r;
        tmR = -s4 * O64i; tmI = s4 * O64r;
    }
#define K2OUT(FQ, CR, CI, SR, SI)                                                        \
    g_X2[obase + (31 + (FQ)) * 32 + ky] =                                                \
        make_float2(baseR + tpR + (CR) + (SI), baseI + tpI + (CI) - (SR));               \
    if ((FQ) > 0)                                                                        \
        g_X2[obase + (31 - (FQ)) * 32 + ky] =                                            \
            make_float2(baseR + tmR + (CR) - (SI), baseI + tmI + (CI) + (SR));
    K2OUT(g,      Cr0, Ci0, Sr0, Si0)
    K2OUT(g + 16, Cr1, Ci1, Sr1, Si1)
#undef K2OUT
}

// ---------------- K3: channel mix, 4 (f,ky) tiles/block, 4b x 4o register blocking ----
// X2 is [bi][fk]: one 32B sector per bi holds the block's 4 consecutive fk values.
__global__ __launch_bounds__(256, 4) void sc_k3() {
    __shared__ __align__(16) float2 sX[4 * 1024];   // [tile][bi]; reused as stage
    int tid = threadIdx.x, bid = blockIdx.x;        // bid covers fk0 = bid*4
    int tile = tid >> 6, t = tid & 63;
    int og = t & 15, bg = t >> 4;
    int fk = bid * 4 + tile;
    int fk0 = bid * 4;
    for (int q = tid; q < 1024; q += 256) {         // q = bi
        const float4* src = (const float4*)(g_X2 + (size_t)q * 2016 + fk0);
        float4 a = src[0];                          // fk0+0, fk0+1
        float4 b = src[1];                          // fk0+2, fk0+3
        sX[q]        = make_float2(a.x, a.y);
        sX[1024 + q] = make_float2(a.z, a.w);
        sX[2048 + q] = make_float2(b.x, b.y);
        sX[3072 + q] = make_float2(b.z, b.w);
    }
    __syncthreads();

    float ar[4][4], ai[4][4];
#pragma unroll
    for (int bb = 0; bb < 4; bb++)
#pragma unroll
        for (int oo = 0; oo < 4; oo++) { ar[bb][oo] = 0.f; ai[bb][oo] = 0.f; }

    const float2* Wbase = g_W + (size_t)fk * 4096 + og * 4;
    const float2* Xbase = sX + tile * 1024 + bg * 4 * 64;
#pragma unroll 4
    for (int i = 0; i < 64; i++) {
        float4 w01 = __ldg((const float4*)(Wbase + i * 64));
        float4 w23 = __ldg((const float4*)(Wbase + i * 64 + 2));
        float2 v0 = Xbase[i];
        float2 v1 = Xbase[64 + i];
        float2 v2 = Xbase[128 + i];
        float2 v3 = Xbase[192 + i];
#define CMAC(BB, V)                                                          \
        ar[BB][0] += V.x*w01.x - V.y*w01.y;  ai[BB][0] += V.x*w01.y + V.y*w01.x; \
        ar[BB][1] += V.x*w01.z - V.y*w01.w;  ai[BB][1] += V.x*w01.w + V.y*w01.z; \
        ar[BB][2] += V.x*w23.x - V.y*w23.y;  ai[BB][2] += V.x*w23.y + V.y*w23.x; \
        ar[BB][3] += V.x*w23.z - V.y*w23.w;  ai[BB][3] += V.x*w23.w + V.y*w23.z;
        CMAC(0, v0) CMAC(1, v1) CMAC(2, v2) CMAC(3, v3)
#undef CMAC
    }
    __syncthreads();
#pragma unroll
    for (int bb = 0; bb < 4; bb++)
#pragma unroll
        for (int oo = 0; oo < 4; oo++) {
            int bo = (bg * 4 + bb) * 64 + og * 4 + oo;
            sX[bo * 4 + tile] = make_float2(ar[bb][oo], ai[bb][oo]);
        }
    __syncthreads();
    for (int q = tid; q < 2048; q += 256) {
        int bo = q >> 1, half = q & 1;
        float4 val = *(const float4*)(sX + bo * 4 + half * 2);
        *(float4*)(g_X3 + (size_t)bo * 2016 + fk0 + half * 2) = val;
    }
}

// ---------------- K45: fused iDFT-x + irfft-y per (b,o); 8 rows/thread phase 2 -------
#define SMEM45 ((8192 + 2016 + 992 + 992 + 264) * 8)
__global__ __launch_bounds__(256, 2) void sc_k45(float* __restrict__ out) {
    extern __shared__ float smf[];
    float2* sYt  = (float2*)smf;            // [x(256)][ky(32)]
    float2* sX3  = sYt + 8192;              // 2016
    float2* sU   = sX3 + 2016;              // 992
    float2* sV   = sU + 992;                // 992
    float2* stab = sV + 992;                // 264
    int tid = threadIdx.x, bid = blockIdx.x;            // bid = b*64+o

    // ---- phase 1: iDFT along x -> sYt ----
    {
        const float4* src = (const float4*)(g_X3 + (size_t)bid * 2016);
        float4* dst = (float4*)sX3;
        for (int q = tid; q < 1008; q += 256) dst[q] = src[q];
        for (int q = tid; q < 264; q += 256) stab[q] = g_tab[q];
    }
    __syncthreads();
    for (int e = tid; e < 992; e += 256) {
        int ky = e & 31, fq = (e >> 5) + 1;
        float2 P = sX3[(31 + fq) * 32 + ky];
        float2 Q = sX3[(31 - fq) * 32 + ky];
        sU[e] = make_float2(P.x + Q.x, P.y + Q.y);
        sV[e] = make_float2(-(P.y - Q.y), P.x - Q.x);   // i*(P-Q)
    }
    __syncthreads();

    {
        int ky4 = (tid & 7) * 4, xs = tid >> 3;
        const float4* m = (const float4*)(sX3 + 31 * 32 + ky4);
        float4 m01 = m[0], m23 = m[1];
        for (int xi = 0; xi < 4; xi++) {
            int xx = xs + 32 * xi;
            float c0 = m01.x, c1 = m01.y, c2 = m01.z, c3 = m01.w;
            float c4 = m23.x, c5 = m23.y, c6 = m23.z, c7 = m23.w;
            float s0 = 0, s1 = 0, s2 = 0, s3 = 0, s4 = 0, s5 = 0, s6 = 0, s7 = 0;
            int p = 0;
#pragma unroll 4
            for (int fq = 1; fq < 32; fq++) {
                p = (p + xx) & 255;
                float2 t = stab[tp(p)];
                const float4* up = (const float4*)(sU + (fq - 1) * 32 + ky4);
                const float4* vp = (const float4*)(sV + (fq - 1) * 32 + ky4);
                float4 u01 = up[0], u23 = up[1], v01 = vp[0], v23 = vp[1];
                c0 += t.x * u01.x;  s0 += t.y * v01.x;
                c1 += t.x * u01.y;  s1 += t.y * v01.y;
                c2 += t.x * u01.z;  s2 += t.y * v01.z;
                c3 += t.x * u01.w;  s3 += t.y * v01.w;
                c4 += t.x * u23.x;  s4 += t.y * v23.x;
                c5 += t.x * u23.y;  s5 += t.y * v23.y;
                c6 += t.x * u23.z;  s6 += t.y * v23.z;
                c7 += t.x * u23.w;  s7 += t.y * v23.w;
            }
            float4* o1 = (float4*)(sYt + xx * 32 + ky4);
            o1[0] = make_float4(c0 + s0, c1 + s1, c2 + s2, c3 + s3);
            o1[1] = make_float4(c4 + s4, c5 + s5, c6 + s6, c7 + s7);
            if (xx > 0) {
                float4* o2 = (float4*)(sYt + (256 - xx) * 32 + ky4);
                o2[0] = make_float4(c0 - s0, c1 - s1, c2 - s2, c3 - s3);
                o2[1] = make_float4(c4 - s4, c5 - s5, c6 - s6, c7 - s7);
            }
        }
        if (tid < 32) {
            int ky = tid;
            float2 acc = sX3[31 * 32 + ky];
#pragma unroll 4
            for (int fq = 1; fq < 32; fq++) {
                float2 u = sU[(fq - 1) * 32 + ky];
                float sg = (fq & 1) ? -1.f : 1.f;
                acc.x += sg * u.x;  acc.y += sg * u.y;
            }
            sYt[128 * 32 + ky] = acc;
        }
    }
    __syncthreads();

    // ---- phase 2: irfft along y, 8 rows/thread, 4 outer iterations ----
    int l = tid & 31, w = tid >> 5;
    float2 tA = __ldg(&g_tw1[l]);
    const float R45 = 0.70710678118654752f;
    float cB1 = (tA.x - tA.y) * R45;
    float sB1 = (tA.x + tA.y) * R45;
    float KA = 2.f * tA.x, KB = 2.f * cB1;
    const float SC1 = 1.f / 256.f, SC2 = 2.f / 256.f;

    for (int rgh = 0; rgh < 4; rgh++) {
        const float2* sY = sYt + (rgh * 64 + w * 8) * 32;   // 8 rows for this thread
        float cAc = 1.f, cAp = tA.x;
        float zAc = 0.f, zAp = -tA.y;
        float cBc = 1.f, cBp = cB1;
        float zBc = 0.f, zBp = -sB1;

        float Ae0[8]={0,0,0,0,0,0,0,0}, Se0[8]={0,0,0,0,0,0,0,0};
        float Ao0[8]={0,0,0,0,0,0,0,0}, So0[8]={0,0,0,0,0,0,0,0};
        float Ae1[8]={0,0,0,0,0,0,0,0}, Se1[8]={0,0,0,0,0,0,0,0};
        float Ao1[8]={0,0,0,0,0,0,0,0}, So1[8]={0,0,0,0,0,0,0,0};

#pragma unroll 4
        for (int kp = 0; kp < 16; kp++) {
            float n;
            n = KA * cAc - cAp;  cAp = cAc;  cAc = n;
            n = KA * zAc - zAp;  zAp = zAc;  zAc = n;
            n = KB * cBc - cBp;  cBp = cBc;  cBc = n;
            n = KB * zBc - zBp;  zBp = zBc;  zBc = n;
            int kyo = 2 * kp + 1;
#pragma unroll
            for (int r = 0; r < 8; r++) {
                float2 v = sY[r * 32 + kyo];
                Ao0[r] += v.x * cAc;  So0[r] += v.y * zAc;
                Ao1[r] += v.x * cBc;  So1[r] += v.y * zBc;
            }
            if (kp < 15) {
                n = KA * cAc - cAp;  cAp = cAc;  cAc = n;
                n = KA * zAc - zAp;  zAp = zAc;  zAc = n;
                n = KB * cBc - cBp;  cBp = cBc;  cBc = n;
                n = KB * zBc - zBp;  zBp = zBc;  zBc = n;
                int kye = 2 * kp + 2;
#pragma unroll
                for (int r = 0; r < 8; r++) {
                    float2 v = sY[r * 32 + kye];
                    Ae0[r] += v.x * cAc;  Se0[r] += v.y * zAc;
                    Ae1[r] += v.x * cBc;  Se1[r] += v.y * zBc;
                }
            }
        }

#pragma unroll
        for (int r = 0; r < 8; r++) {
            size_t ob = ((size_t)bid * 256 + rgh * 64 + w * 8 + r) * 256;
            float bx = sY[r * 32].x * SC1;
            float a  = SC2 * (Ae0[r] + Ao0[r]) + bx;
            float s  = SC2 * (Se0[r] + So0[r]);
            float am = SC2 * (Ae0[r] - Ao0[r]) + bx;
            float sm = SC2 * (Se0[r] - So0[r]);
            out[ob + l]       = a - s;
            out[ob + 128 - l] = am + sm;
            if (l > 0) {
                out[ob + 256 - l] = a + s;
                out[ob + 128 + l] = am - sm;
            }
            float a1  = SC2 * (Ae1[r] + Ao1[r]) + bx;
            float s1  = SC2 * (Se1[r] + So1[r]);
            float am1 = SC2 * (Ae1[r] - Ao1[r]) + bx;
            float sm1 = SC2 * (Se1[r] - So1[r]);
            out[ob + 32 + l]  = a1 - s1;
            out[ob + 224 - l] = a1 + s1;
            out[ob + 96 - l]  = am1 + sm1;
            out[ob + 160 + l] = am1 - sm1;
        }
        // tail t = 64 / 192 for these 8 rows
        {
            int ky = l;
            float sc = (ky == 0) ? SC1 : SC2;
            int m4 = ky & 3;
            float c64 = (m4 == 0) ? sc : (m4 == 2 ? -sc : 0.f);
            float s64 = (m4 == 1) ? sc : (m4 == 3 ? -sc : 0.f);
#pragma unroll
            for (int r = 0; r < 8; r++) {
                float2 v = sY[r * 32 + ky];
                float p = v.x * c64 - v.y * s64;
                float q = v.x * c64 + v.y * s64;
#pragma unroll
                for (int off = 16; off; off >>= 1) {
                    p += __shfl_xor_sync(0xFFFFFFFFu, p, off);
                    q += __shfl_xor_sync(0xFFFFFFFFu, q, off);
                }
                if (l == 0) {
                    size_t ob = ((size_t)bid * 256 + rgh * 64 + w * 8 + r) * 256;
                    out[ob + 64]  = p;
                    out[ob + 192] = q;
                }
            }
        }
    }
}

// ---------------- launch: fork W-build onto a side stream, overlap with K12 ----------
extern "C" void kernel_launch(void* const* d_in, const int* in_sizes, int n_in,
                              void* d_out, int out_size) {
    const float* x   = (const float*)d_in[0];
    const float* y0r = (const float*)d_in[1];
    const float* y0i = (const float*)d_in[2];
    const float* ypr = (const float*)d_in[3];
    const float* ypi = (const float*)d_in[4];
    const float* w00 = (const float*)d_in[5];
    float* out = (float*)d_out;

    cudaFuncSetAttribute(sc_k12, cudaFuncAttributeMaxDynamicSharedMemorySize, SMEM12);
    cudaFuncSetAttribute(sc_k45, cudaFuncAttributeMaxDynamicSharedMemorySize, SMEM45);

    cudaStream_t s2;
    cudaEvent_t evF, evJ;
    cudaStreamCreateWithFlags(&s2, cudaStreamNonBlocking);
    cudaEventCreateWithFlags(&evF, cudaEventDisableTiming);
    cudaEventCreateWithFlags(&evJ, cudaEventDisableTiming);

    // fork: side stream joins the capture graph at the root
    cudaEventRecord(evF, 0);
    cudaStreamWaitEvent(s2, evF, 0);

    // side stream: W build (feeds only K3)
    sc_build_w0<<<(63 * 4096 + 255) / 256, 256, 0, s2>>>(y0r, y0i, w00);
    sc_build_wt<<<dim3(62, 128), dim3(32, 8), 0, s2>>>(ypr, ypi);
    cudaEventRecord(evJ, s2);

    // main stream: tables -> K12
    sc_tabs<<<9, 256>>>();
    sc_k12<<<1024, 512, SMEM12>>>(x);

    // join before K3 (needs g_W and g_X2)
    cudaStreamWaitEvent(0, evJ, 0);
    sc_k3<<<504, 256>>>();
    sc_k45<<<1024, 256, SMEM45>>>(out);
}

// round 16
// speedup vs baseline: 1.6863x; 1.0188x over previous
#include <cuda_runtime.h>
#include <cuda_fp16.h>
#include <cstdint>

// Problem dims (fixed): B=16, Ci=Co=64, S=256, m1=m2=32
// ---------------- device scratch (no allocs allowed) ----------------
__device__ __align__(16) float2 g_tab[264];                       // padded cos/sin table (K45 ph1)
__device__ __align__(16) float2 g_tw1[63*32];                     // [s-1][ky] twiddles
__device__ __align__(16) __half2 g_W[63*32*64*64];                // [fk][io] complex weights, fp16
__device__ __align__(16) float2 g_X2[16*64*2016];                 // [bi][fk]  (fk = f*32+ky)
__device__ __align__(16) float2 g_X3[16*64*63*32];                // [b][o][f][ky]

__device__ __forceinline__ int tp(int i) { return i + (i >> 5); }

// ---------------- init: all tables ----------------
__global__ void sc_tabs() {
    int t = blockIdx.x * 256 + threadIdx.x;
    if (t < 264) {
        int k = t / 33;
        int idx = t - k;
        float ang = (float)(6.283185307179586 * (double)idx / 256.0);
        g_tab[t] = make_float2(cosf(ang), sinf(ang));
    }
    int e1 = t - 264;
    if (e1 >= 0 && e1 < 63 * 32) {
        int s = (e1 >> 5) + 1, ky = e1 & 31;           // s = 1..63
        double ang = 6.283185307179586 * (double)((ky * s) % 256) / 256.0;
        g_tw1[e1] = make_float2((float)cos(ang), (float)sin(ang));
    }
}

// ---------------- build W: ky=0 plane (fp16) ----------------
__global__ void sc_build_w0(const float* __restrict__ y0r, const float* __restrict__ y0i,
                            const float* __restrict__ w00) {
    int t = blockIdx.x * 256 + threadIdx.x;
    if (t >= 63 * 4096) return;
    int io = t & 4095;
    int f  = t >> 12;
    float wr, wi;
    if (f < 31)       { wr = y0r[io * 31 + f];        wi = y0i[io * 31 + f]; }
    else if (f == 31) { wr = w00[io];                 wi = 0.f; }
    else              { wr = y0r[io * 31 + (62 - f)]; wi = -y0i[io * 31 + (62 - f)]; }
    g_W[(size_t)(f * 32) * 4096 + io] = __floats2half2_rn(wr, wi);
}

// ---------------- build W: ky>=1 planes via tiled transpose (fp16 out) ----------------
__global__ void sc_build_wt(const float* __restrict__ ypr, const float* __restrict__ ypi) {
    __shared__ float2 tile[32][33];
    int tx = threadIdx.x, ty = threadIdx.y;        // 32 x 8
    int fk0 = blockIdx.x * 32, io0 = blockIdx.y * 32;
#pragma unroll
    for (int k = 0; k < 4; k++) {
        int io = io0 + ty + 8 * k;
        int fk = fk0 + tx;
        if (fk < 1953)
            tile[ty + 8 * k][tx] = make_float2(ypr[(size_t)io * 1953 + fk],
                                               ypi[(size_t)io * 1953 + fk]);
    }
    __syncthreads();
#pragma unroll
    for (int k = 0; k < 4; k++) {
        int fk = fk0 + ty + 8 * k;
        if (fk < 1953) {
            int f  = fk / 31;
            int ky = fk - f * 31 + 1;
            float2 v = tile[tx][ty + 8 * k];
            g_W[(size_t)(f * 32 + ky) * 4096 + io0 + tx] = __floats2half2_rn(v.x, v.y);
        }
    }
}

// ---------------- K12: fused DFT-y + DFT-x per (b,i) image (round-8 version) ----------
// X2 stores are [bi][fk]-coalesced.
#define SMEM12 ((4*64*130 + 256*4) * 4 + 256*32*8)
__global__ __launch_bounds__(512, 1) void sc_k12(const float* __restrict__ x) {
    extern __shared__ float sm12[];
    float* sEp = sm12;                    // [s(0..63)][slot(130 pad, 128 used)]
    float* sEm = sEp + 64 * 130;
    float* sOp = sEm + 64 * 130;
    float* sOm = sOp + 64 * 130;
    float* sbase = sOm + 64 * 130;        // [row(256)][4]
    float2* sX1 = (float2*)(sbase + 1024);// [x(256)][ky(32)]
    int tid = threadIdx.x, bid = blockIdx.x;      // bid = b*64 + i
    int lane = tid & 31, w = tid >> 5;            // w = 0..15
    const float* gx = x + (size_t)bid * 65536;
    int sp = (32 - lane) & 31;

    // ---- phase 1: DFT along y, warp-local ----
    int ky0 = lane & 7, rp2 = lane >> 3;
    int slot0 = 8 * w + 2 * rp2;
    int p1q = ky0 & 1;
    float sgn1 = p1q ? -1.f : 1.f;
    int m41 = ky0 & 3;
    float c64a = (m41 == 0) ? 1.f : (m41 == 2 ? -1.f : 0.f);
    float s64a = (m41 == 1) ? 1.f : (m41 == 3 ? -1.f : 0.f);
    const float* EE = p1q ? sEm : sEp;
    const float* OO = p1q ? sOp : sOm;
    float Kk[4], t1x[4], t1y[4];
#pragma unroll
    for (int j = 0; j < 4; j++) {
        float2 t1 = __ldg(&g_tw1[ky0 + 8 * j]);
        Kk[j] = 2.f * t1.x;  t1x[j] = t1.x;  t1y[j] = t1.y;
    }

    for (int it = 0; it < 2; it++) {
        int rowbase = 8 * w + 128 * it;
#pragma unroll
        for (int r = 0; r < 8; r++) {
            int row = rowbase + r;
            int slot = 8 * w + r;
            const float* rp = gx + row * 256;
            float v[8];
#pragma unroll
            for (int k = 0; k < 8; k++) v[k] = rp[lane + 32 * k];
            float E1[4], O1[4];
#pragma unroll
            for (int k = 0; k < 4; k++) {
                float p1 = __shfl_sync(0xFFFFFFFFu, v[7 - k], sp);
                if (lane == 0) p1 = v[(8 - k) & 7];
                E1[k] = v[k] + p1;
                O1[k] = v[k] - p1;
            }
#pragma unroll
            for (int k = 0; k < 2; k++) {
                int c = lane + 32 * k;
                float qe = __shfl_sync(0xFFFFFFFFu, E1[3 - k], sp);
                float qo = __shfl_sync(0xFFFFFFFFu, O1[3 - k], sp);
                if (k == 1 && lane == 0) { qe = E1[3]; qo = O1[3]; }
                float ep = E1[k] + qe, em = E1[k] - qe;
                float op = O1[k] + qo, om = O1[k] - qo;
                if (c >= 1 && c <= 63) {
                    sEp[c * 130 + slot] = ep;
                    sEm[c * 130 + slot] = em;
                    sOp[c * 130 + slot] = op;
                    sOm[c * 130 + slot] = om;
                }
            }
            if (lane == 0) {
                sbase[row * 4 + 0] = v[0];
                sbase[row * 4 + 1] = v[4];
                sbase[row * 4 + 2] = v[2] + v[6];
                sbase[row * 4 + 3] = v[2] - v[6];
            }
        }
        __syncwarp();

        int row0 = slot0 + 128 * it;
        float cp[4], cc[4], zp[4], zc[4];
#pragma unroll
        for (int j = 0; j < 4; j++) {
            cp[j] = 1.f;  cc[j] = t1x[j];
            zp[j] = 0.f;  zc[j] = t1y[j];
        }
        float re[4][2], im[4][2];
        {
            const float* b0 = sbase + row0 * 4;
            const float* b1 = sbase + (row0 + 1) * 4;
            float base0 = b0[0] + sgn1 * b0[1] + c64a * b0[2];
            float base1 = b1[0] + sgn1 * b1[1] + c64a * b1[2];
            float imb0 = -s64a * b0[3];
            float imb1 = -s64a * b1[3];
#pragma unroll
            for (int j = 0; j < 4; j++) {
                re[j][0] = base0;  re[j][1] = base1;
                im[j][0] = imb0;   im[j][1] = imb1;
            }
        }
#pragma unroll 7
        for (int s = 1; s < 64; s++) {
            float2 e = *(const float2*)(EE + s * 130 + slot0);
            float2 o = *(const float2*)(OO + s * 130 + slot0);
#pragma unroll
            for (int j = 0; j < 4; j++) {
                re[j][0] += e.x * cc[j];  im[j][0] -= o.x * zc[j];
                re[j][1] += e.y * cc[j];  im[j][1] -= o.y * zc[j];
                float cn = Kk[j] * cc[j] - cp[j];  cp[j] = cc[j];  cc[j] = cn;
                float zn = Kk[j] * zc[j] - zp[j];  zp[j] = zc[j];  zc[j] = zn;
            }
        }
        const float SC = 1.f / 256.f;
#pragma unroll
        for (int j = 0; j < 4; j++) {
            int ky = ky0 + 8 * j;
#pragma unroll
            for (int r = 0; r < 2; r++)
                sX1[(row0 + r) * 32 + ky] = make_float2(re[j][r] * SC, im[j][r] * SC);
        }
        __syncwarp();
    }
    __syncthreads();

    // ---- phase 2: 4x fold in x (in place) ----
    for (int e = tid; e < 63 * 32; e += 512) {
        int xx = (e >> 5) + 1, ky = e & 31;
        float2 a = sX1[xx * 32 + ky];
        float2 b = sX1[(256 - xx) * 32 + ky];
        float2 c = sX1[(128 - xx) * 32 + ky];
        float2 d = sX1[(128 + xx) * 32 + ky];
        sX1[xx * 32 + ky]         = make_float2(a.x + b.x + c.x + d.x, a.y + b.y + c.y + d.y);
        sX1[(256 - xx) * 32 + ky] = make_float2(a.x + b.x - c.x - d.x, a.y + b.y - c.y - d.y);
        sX1[(128 - xx) * 32 + ky] = make_float2(a.x - b.x + c.x - d.x, a.y - b.y + c.y - d.y);
        sX1[(128 + xx) * 32 + ky] = make_float2(a.x - b.x - c.x + d.x, a.y - b.y - c.y + d.y);
    }
    __syncthreads();

    // ---- phase 2: DFT along x (63 terms), 2 freqs per thread ----
    int ky = tid & 31, g = tid >> 5;          // g = 0..15, freqs {g, g+16}
    size_t obase = (size_t)bid * 2016;        // [bi][fk] layout
    int p = g & 1;
    float Cr0=0,Ci0=0,Sr0=0,Si0=0, Cr1=0,Ci1=0,Sr1=0,Si1=0;
#pragma unroll 7
    for (int xx = 1; xx < 64; xx++) {
        int eeIdx = (p ? (256 - xx) : xx) * 32 + ky;
        int ooIdx = (p ? (128 - xx) : (128 + xx)) * 32 + ky;
        float2 e = sX1[eeIdx];
        float2 o = sX1[ooIdx];
        const float2* twr = &g_tw1[(xx - 1) * 32];
        float2 t0 = __ldg(twr + g);
        float2 t1 = __ldg(twr + g + 16);
        Cr0 += e.x*t0.x; Ci0 += e.y*t0.x; Sr0 += o.x*t0.y; Si0 += o.y*t0.y;
        Cr1 += e.x*t1.x; Ci1 += e.y*t1.x; Sr1 += o.x*t1.y; Si1 += o.y*t1.y;
    }
    float2 b0   = sX1[0 * 32 + ky];
    float2 b128 = sX1[128 * 32 + ky];
    float2 x64  = sX1[64 * 32 + ky];
    float2 x192 = sX1[192 * 32 + ky];
    float sgnB = p ? -1.f : 1.f;
    float baseR = b0.x + sgnB * b128.x, baseI = b0.y + sgnB * b128.y;
    float E64r = x64.x + x192.x, E64i = x64.y + x192.y;
    float O64r = x64.x - x192.x, O64i = x64.y - x192.y;
    float tpR, tpI, tmR, tmI;
    int gm4 = g & 3;
    if (!p) {
        float c4 = (gm4 == 0) ? 1.f : -1.f;
        tpR = tmR = c4 * E64r;  tpI = tmI = c4 * E64i;
    } else {
        float s4 = (gm4 == 1) ? 1.f : -1.f;
        tpR = s4 * O64i;  tpI = -s4 * O64r;
        tmR = -s4 * O64i; tmI = s4 * O64r;
    }
#define K2OUT(FQ, CR, CI, SR, SI)                                                        \
    g_X2[obase + (31 + (FQ)) * 32 + ky] =                                                \
        make_float2(baseR + tpR + (CR) + (SI), baseI + tpI + (CI) - (SR));               \
    if ((FQ) > 0)                                                                        \
        g_X2[obase + (31 - (FQ)) * 32 + ky] =                                            \
            make_float2(baseR + tmR + (CR) - (SI), baseI + tmI + (CI) + (SR));
    K2OUT(g,      Cr0, Ci0, Sr0, Si0)
    K2OUT(g + 16, Cr1, Ci1, Sr1, Si1)
#undef K2OUT
}

// ---------------- K3: channel mix, 4 (f,ky) tiles/block, fp16 W (one LDG.128/iter) ---
__global__ __launch_bounds__(256, 4) void sc_k3() {
    __shared__ __align__(16) float2 sX[4 * 1024];   // [tile][bi]; reused as stage
    int tid = threadIdx.x, bid = blockIdx.x;        // bid covers fk0 = bid*4
    int tile = tid >> 6, t = tid & 63;
    int og = t & 15, bg = t >> 4;
    int fk = bid * 4 + tile;
    int fk0 = bid * 4;
    for (int q = tid; q < 1024; q += 256) {         // q = bi
        const float4* src = (const float4*)(g_X2 + (size_t)q * 2016 + fk0);
        float4 a = src[0];                          // fk0+0, fk0+1
        float4 b = src[1];                          // fk0+2, fk0+3
        sX[q]        = make_float2(a.x, a.y);
        sX[1024 + q] = make_float2(a.z, a.w);
        sX[2048 + q] = make_float2(b.x, b.y);
        sX[3072 + q] = make_float2(b.z, b.w);
    }
    __syncthreads();

    float ar[4][4], ai[4][4];
#pragma unroll
    for (int bb = 0; bb < 4; bb++)
#pragma unroll
        for (int oo = 0; oo < 4; oo++) { ar[bb][oo] = 0.f; ai[bb][oo] = 0.f; }

    const __half2* Wbase = g_W + (size_t)fk * 4096 + og * 4;
    const float2* Xbase = sX + tile * 1024 + bg * 4 * 64;
#pragma unroll 4
    for (int i = 0; i < 64; i++) {
        float4 raw = __ldg((const float4*)(Wbase + i * 64));   // 4 complex fp16 weights
        const __half2* hp = (const __half2*)&raw;
        float2 w0 = __half22float2(hp[0]);
        float2 w1 = __half22float2(hp[1]);
        float2 w2 = __half22float2(hp[2]);
        float2 w3 = __half22float2(hp[3]);
        float2 v0 = Xbase[i];
        float2 v1 = Xbase[64 + i];
        float2 v2 = Xbase[128 + i];
        float2 v3 = Xbase[192 + i];
#define CMAC(BB, V)                                                          \
        ar[BB][0] += V.x*w0.x - V.y*w0.y;  ai[BB][0] += V.x*w0.y + V.y*w0.x; \
        ar[BB][1] += V.x*w1.x - V.y*w1.y;  ai[BB][1] += V.x*w1.y + V.y*w1.x; \
        ar[BB][2] += V.x*w2.x - V.y*w2.y;  ai[BB][2] += V.x*w2.y + V.y*w2.x; \
        ar[BB][3] += V.x*w3.x - V.y*w3.y;  ai[BB][3] += V.x*w3.y + V.y*w3.x;
        CMAC(0, v0) CMAC(1, v1) CMAC(2, v2) CMAC(3, v3)
#undef CMAC
    }
    __syncthreads();
#pragma unroll
    for (int bb = 0; bb < 4; bb++)
#pragma unroll
        for (int oo = 0; oo < 4; oo++) {
            int bo = (bg * 4 + bb) * 64 + og * 4 + oo;
            sX[bo * 4 + tile] = make_float2(ar[bb][oo], ai[bb][oo]);
        }
    __syncthreads();
    for (int q = tid; q < 2048; q += 256) {
        int bo = q >> 1, half = q & 1;
        float4 val = *(const float4*)(sX + bo * 4 + half * 2);
        *(float4*)(g_X3 + (size_t)bo * 2016 + fk0 + half * 2) = val;
    }
}

// ---------------- K45: fused iDFT-x + irfft-y per (b,o); 8 rows/thread phase 2 -------
#define SMEM45 ((8192 + 2016 + 992 + 992 + 264) * 8)
__global__ __launch_bounds__(256, 2) void sc_k45(float* __restrict__ out) {
    extern __shared__ float smf[];
    float2* sYt  = (float2*)smf;            // [x(256)][ky(32)]
    float2* sX3  = sYt + 8192;              // 2016
    float2* sU   = sX3 + 2016;              // 992
    float2* sV   = sU + 992;                // 992
    float2* stab = sV + 992;                // 264
    int tid = threadIdx.x, bid = blockIdx.x;            // bid = b*64+o

    // ---- phase 1: iDFT along x -> sYt ----
    {
        const float4* src = (const float4*)(g_X3 + (size_t)bid * 2016);
        float4* dst = (float4*)sX3;
        for (int q = tid; q < 1008; q += 256) dst[q] = src[q];
        for (int q = tid; q < 264; q += 256) stab[q] = g_tab[q];
    }
    __syncthreads();
    for (int e = tid; e < 992; e += 256) {
        int ky = e & 31, fq = (e >> 5) + 1;
        float2 P = sX3[(31 + fq) * 32 + ky];
        float2 Q = sX3[(31 - fq) * 32 + ky];
        sU[e] = make_float2(P.x + Q.x, P.y + Q.y);
        sV[e] = make_float2(-(P.y - Q.y), P.x - Q.x);   // i*(P-Q)
    }
    __syncthreads();

    {
        int ky4 = (tid & 7) * 4, xs = tid >> 3;
        const float4* m = (const float4*)(sX3 + 31 * 32 + ky4);
        float4 m01 = m[0], m23 = m[1];
        for (int xi = 0; xi < 4; xi++) {
            int xx = xs + 32 * xi;
            float c0 = m01.x, c1 = m01.y, c2 = m01.z, c3 = m01.w;
            float c4 = m23.x, c5 = m23.y, c6 = m23.z, c7 = m23.w;
            float s0 = 0, s1 = 0, s2 = 0, s3 = 0, s4 = 0, s5 = 0, s6 = 0, s7 = 0;
            int p = 0;
#pragma unroll 4
            for (int fq = 1; fq < 32; fq++) {
                p = (p + xx) & 255;
                float2 t = stab[tp(p)];
                const float4* up = (const float4*)(sU + (fq - 1) * 32 + ky4);
                const float4* vp = (const float4*)(sV + (fq - 1) * 32 + ky4);
                float4 u01 = up[0], u23 = up[1], v01 = vp[0], v23 = vp[1];
                c0 += t.x * u01.x;  s0 += t.y * v01.x;
                c1 += t.x * u01.y;  s1 += t.y * v01.y;
                c2 += t.x * u01.z;  s2 += t.y * v01.z;
                c3 += t.x * u01.w;  s3 += t.y * v01.w;
                c4 += t.x * u23.x;  s4 += t.y * v23.x;
                c5 += t.x * u23.y;  s5 += t.y * v23.y;
                c6 += t.x * u23.z;  s6 += t.y * v23.z;
                c7 += t.x * u23.w;  s7 += t.y * v23.w;
            }
            float4* o1 = (float4*)(sYt + xx * 32 + ky4);
            o1[0] = make_float4(c0 + s0, c1 + s1, c2 + s2, c3 + s3);
            o1[1] = make_float4(c4 + s4, c5 + s5, c6 + s6, c7 + s7);
            if (xx > 0) {
                float4* o2 = (float4*)(sYt + (256 - xx) * 32 + ky4);
                o2[0] = make_float4(c0 - s0, c1 - s1, c2 - s2, c3 - s3);
                o2[1] = make_float4(c4 - s4, c5 - s5, c6 - s6, c7 - s7);
            }
        }
        if (tid < 32) {
            int ky = tid;
            float2 acc = sX3[31 * 32 + ky];
#pragma unroll 4
            for (int fq = 1; fq < 32; fq++) {
                float2 u = sU[(fq - 1) * 32 + ky];
                float sg = (fq & 1) ? -1.f : 1.f;
                acc.x += sg * u.x;  acc.y += sg * u.y;
            }
            sYt[128 * 32 + ky] = acc;
        }
    }
    __syncthreads();

    // ---- phase 2: irfft along y, 8 rows/thread, 4 outer iterations ----
    int l = tid & 31, w = tid >> 5;
    float2 tA = __ldg(&g_tw1[l]);
    const float R45 = 0.70710678118654752f;
    float cB1 = (tA.x - tA.y) * R45;
    float sB1 = (tA.x + tA.y) * R45;
    float KA = 2.f * tA.x, KB = 2.f * cB1;
    const float SC1 = 1.f / 256.f, SC2 = 2.f / 256.f;

    for (int rgh = 0; rgh < 4; rgh++) {
        const float2* sY = sYt + (rgh * 64 + w * 8) * 32;   // 8 rows for this thread
        float cAc = 1.f, cAp = tA.x;
        float zAc = 0.f, zAp = -tA.y;
        float cBc = 1.f, cBp = cB1;
        float zBc = 0.f, zBp = -sB1;

        float Ae0[8]={0,0,0,0,0,0,0,0}, Se0[8]={0,0,0,0,0,0,0,0};
        float Ao0[8]={0,0,0,0,0,0,0,0}, So0[8]={0,0,0,0,0,0,0,0};
        float Ae1[8]={0,0,0,0,0,0,0,0}, Se1[8]={0,0,0,0,0,0,0,0};
        float Ao1[8]={0,0,0,0,0,0,0,0}, So1[8]={0,0,0,0,0,0,0,0};

#pragma unroll 4
        for (int kp = 0; kp < 16; kp++) {
            float n;
            n = KA * cAc - cAp;  cAp = cAc;  cAc = n;
            n = KA * zAc - zAp;  zAp = zAc;  zAc = n;
            n = KB * cBc - cBp;  cBp = cBc;  cBc = n;
            n = KB * zBc - zBp;  zBp = zBc;  zBc = n;
            int kyo = 2 * kp + 1;
#pragma unroll
            for (int r = 0; r < 8; r++) {
                float2 v = sY[r * 32 + kyo];
                Ao0[r] += v.x * cAc;  So0[r] += v.y * zAc;
                Ao1[r] += v.x * cBc;  So1[r] += v.y * zBc;
            }
            if (kp < 15) {
                n = KA * cAc - cAp;  cAp = cAc;  cAc = n;
                n = KA * zAc - zAp;  zAp = zAc;  zAc = n;
                n = KB * cBc - cBp;  cBp = cBc;  cBc = n;
                n = KB * zBc - zBp;  zBp = zBc;  zBc = n;
                int kye = 2 * kp + 2;
#pragma unroll
                for (int r = 0; r < 8; r++) {
                    float2 v = sY[r * 32 + kye];
                    Ae0[r] += v.x * cAc;  Se0[r] += v.y * zAc;
                    Ae1[r] += v.x * cBc;  Se1[r] += v.y * zBc;
                }
            }
        }

#pragma unroll
        for (int r = 0; r < 8; r++) {
            size_t ob = ((size_t)bid * 256 + rgh * 64 + w * 8 + r) * 256;
            float bx = sY[r * 32].x * SC1;
            float a  = SC2 * (Ae0[r] + Ao0[r]) + bx;
            float s  = SC2 * (Se0[r] + So0[r]);
            float am = SC2 * (Ae0[r] - Ao0[r]) + bx;
            float sm = SC2 * (Se0[r] - So0[r]);
            out[ob + l]       = a - s;
            out[ob + 128 - l] = am + sm;
            if (l > 0) {
                out[ob + 256 - l] = a + s;
                out[ob + 128 + l] = am - sm;
            }
            float a1  = SC2 * (Ae1[r] + Ao1[r]) + bx;
            float s1  = SC2 * (Se1[r] + So1[r]);
            float am1 = SC2 * (Ae1[r] - Ao1[r]) + bx;
            float sm1 = SC2 * (Se1[r] - So1[r]);
            out[ob + 32 + l]  = a1 - s1;
            out[ob + 224 - l] = a1 + s1;
            out[ob + 96 - l]  = am1 + sm1;
            out[ob + 160 + l] = am1 - sm1;
        }
        // tail t = 64 / 192 for these 8 rows
        {
            int ky = l;
            float sc = (ky == 0) ? SC1 : SC2;
            int m4 = ky & 3;
            float c64 = (m4 == 0) ? sc : (m4 == 2 ? -sc : 0.f);
            float s64 = (m4 == 1) ? sc : (m4 == 3 ? -sc : 0.f);
#pragma unroll
            for (int r = 0; r < 8; r++) {
                float2 v = sY[r * 32 + ky];
                float p = v.x * c64 - v.y * s64;
                float q = v.x * c64 + v.y * s64;
#pragma unroll
                for (int off = 16; off; off >>= 1) {
                    p += __shfl_xor_sync(0xFFFFFFFFu, p, off);
                    q += __shfl_xor_sync(0xFFFFFFFFu, q, off);
                }
                if (l == 0) {
                    size_t ob = ((size_t)bid * 256 + rgh * 64 + w * 8 + r) * 256;
                    out[ob + 64]  = p;
                    out[ob + 192] = q;
                }
            }
        }
    }
}

// ---------------- launch: fork W-build onto a side stream, overlap with K12 ----------
extern "C" void kernel_launch(void* const* d_in, const int* in_sizes, int n_in,
                              void* d_out, int out_size) {
    const float* x   = (const float*)d_in[0];
    const float* y0r = (const float*)d_in[1];
    const float* y0i = (const float*)d_in[2];
    const float* ypr = (const float*)d_in[3];
    const float* ypi = (const float*)d_in[4];
    const float* w00 = (const float*)d_in[5];
    float* out = (float*)d_out;

    cudaFuncSetAttribute(sc_k12, cudaFuncAttributeMaxDynamicSharedMemorySize, SMEM12);
    cudaFuncSetAttribute(sc_k45, cudaFuncAttributeMaxDynamicSharedMemorySize, SMEM45);

    cudaStream_t s2;
    cudaEvent_t evF, evJ;
    cudaStreamCreateWithFlags(&s2, cudaStreamNonBlocking);
    cudaEventCreateWithFlags(&evF, cudaEventDisableTiming);
    cudaEventCreateWithFlags(&evJ, cudaEventDisableTiming);

    // fork: side stream joins the capture graph at the root
    cudaEventRecord(evF, 0);
    cudaStreamWaitEvent(s2, evF, 0);

    // side stream: W build (feeds only K3)
    sc_build_w0<<<(63 * 4096 + 255) / 256, 256, 0, s2>>>(y0r, y0i, w00);
    sc_build_wt<<<dim3(62, 128), dim3(32, 8), 0, s2>>>(ypr, ypi);
    cudaEventRecord(evJ, s2);

    // main stream: tables -> K12
    sc_tabs<<<9, 256>>>();
    sc_k12<<<1024, 512, SMEM12>>>(x);

    // join before K3 (needs g_W and g_X2)
    cudaStreamWaitEvent(0, evJ, 0);
    sc_k3<<<504, 256>>>();
    sc_k45<<<1024, 256, SMEM45>>>(out);
}

// round 17
// speedup vs baseline: 1.7179x; 1.0187x over previous
#include <cuda_runtime.h>
#include <cuda_fp16.h>
#include <cstdint>

// Problem dims (fixed): B=16, Ci=Co=64, S=256, m1=m2=32
// ---------------- device scratch (no allocs allowed) ----------------
__device__ __align__(16) float2 g_tab[264];                       // padded cos/sin table (K45 ph1)
__device__ __align__(16) float2 g_tw1[63*32];                     // [s-1][ky] twiddles
__device__ __align__(16) __half2 g_W[63*32*64*64];                // [fk][io] complex weights, fp16
__device__ __align__(16) float2 g_X2[16*64*2016];                 // [bi][fk]  (fk = f*32+ky)
__device__ __align__(16) float2 g_X3[16*64*63*32];                // [b][o][f][ky]

__device__ __forceinline__ int tp(int i) { return i + (i >> 5); }

// ---------------- init: all tables ----------------
__global__ void sc_tabs() {
    int t = blockIdx.x * 256 + threadIdx.x;
    if (t < 264) {
        int k = t / 33;
        int idx = t - k;
        float ang = (float)(6.283185307179586 * (double)idx / 256.0);
        g_tab[t] = make_float2(cosf(ang), sinf(ang));
    }
    int e1 = t - 264;
    if (e1 >= 0 && e1 < 63 * 32) {
        int s = (e1 >> 5) + 1, ky = e1 & 31;           // s = 1..63
        double ang = 6.283185307179586 * (double)((ky * s) % 256) / 256.0;
        g_tw1[e1] = make_float2((float)cos(ang), (float)sin(ang));
    }
}

// ---------------- build W: ky=0 plane (fp16) ----------------
__global__ void sc_build_w0(const float* __restrict__ y0r, const float* __restrict__ y0i,
                            const float* __restrict__ w00) {
    int t = blockIdx.x * 256 + threadIdx.x;
    if (t >= 63 * 4096) return;
    int io = t & 4095;
    int f  = t >> 12;
    float wr, wi;
    if (f < 31)       { wr = y0r[io * 31 + f];        wi = y0i[io * 31 + f]; }
    else if (f == 31) { wr = w00[io];                 wi = 0.f; }
    else              { wr = y0r[io * 31 + (62 - f)]; wi = -y0i[io * 31 + (62 - f)]; }
    g_W[(size_t)(f * 32) * 4096 + io] = __floats2half2_rn(wr, wi);
}

// ---------------- build W: ky>=1 planes via tiled transpose (fp16 out) ----------------
__global__ void sc_build_wt(const float* __restrict__ ypr, const float* __restrict__ ypi) {
    __shared__ float2 tile[32][33];
    int tx = threadIdx.x, ty = threadIdx.y;        // 32 x 8
    int fk0 = blockIdx.x * 32, io0 = blockIdx.y * 32;
#pragma unroll
    for (int k = 0; k < 4; k++) {
        int io = io0 + ty + 8 * k;
        int fk = fk0 + tx;
        if (fk < 1953)
            tile[ty + 8 * k][tx] = make_float2(ypr[(size_t)io * 1953 + fk],
                                               ypi[(size_t)io * 1953 + fk]);
    }
    __syncthreads();
#pragma unroll
    for (int k = 0; k < 4; k++) {
        int fk = fk0 + ty + 8 * k;
        if (fk < 1953) {
            int f  = fk / 31;
            int ky = fk - f * 31 + 1;
            float2 v = tile[tx][ty + 8 * k];
            g_W[(size_t)(f * 32 + ky) * 4096 + io0 + tx] = __floats2half2_rn(v.x, v.y);
        }
    }
}

// ---------------- K12: fused DFT-y + DFT-x per (b,i) image; fp16 fold arrays ---------
// X2 stores are [bi][fk]-coalesced.
#define SMEM12 (4*64*130*2 + 256*4*4 + 256*32*8)
__global__ __launch_bounds__(512, 1) void sc_k12(const float* __restrict__ x) {
    extern __shared__ __align__(16) char sm12raw[];
    __half* sEp = (__half*)sm12raw;       // [s(0..63)][slot(130 pad, 128 used)], fp16
    __half* sEm = sEp + 64 * 130;
    __half* sOp = sEm + 64 * 130;
    __half* sOm = sOp + 64 * 130;
    float* sbase = (float*)(sOm + 64 * 130);   // [row(256)][4]  (offset 66560, 16B-aligned)
    float2* sX1 = (float2*)(sbase + 1024);     // [x(256)][ky(32)]
    int tid = threadIdx.x, bid = blockIdx.x;      // bid = b*64 + i
    int lane = tid & 31, w = tid >> 5;            // w = 0..15
    const float* gx = x + (size_t)bid * 65536;
    int sp = (32 - lane) & 31;

    // ---- phase 1: DFT along y, warp-local ----
    int ky0 = lane & 7, rp2 = lane >> 3;
    int slot0 = 8 * w + 2 * rp2;
    int p1q = ky0 & 1;
    float sgn1 = p1q ? -1.f : 1.f;
    int m41 = ky0 & 3;
    float c64a = (m41 == 0) ? 1.f : (m41 == 2 ? -1.f : 0.f);
    float s64a = (m41 == 1) ? 1.f : (m41 == 3 ? -1.f : 0.f);
    const __half* EE = p1q ? sEm : sEp;
    const __half* OO = p1q ? sOp : sOm;
    float Kk[4], t1x[4], t1y[4];
#pragma unroll
    for (int j = 0; j < 4; j++) {
        float2 t1 = __ldg(&g_tw1[ky0 + 8 * j]);
        Kk[j] = 2.f * t1.x;  t1x[j] = t1.x;  t1y[j] = t1.y;
    }

    for (int it = 0; it < 2; it++) {
        int rowbase = 8 * w + 128 * it;
#pragma unroll
        for (int r = 0; r < 8; r++) {
            int row = rowbase + r;
            int slot = 8 * w + r;
            const float* rp = gx + row * 256;
            float v[8];
#pragma unroll
            for (int k = 0; k < 8; k++) v[k] = rp[lane + 32 * k];
            float E1[4], O1[4];
#pragma unroll
            for (int k = 0; k < 4; k++) {
                float p1 = __shfl_sync(0xFFFFFFFFu, v[7 - k], sp);
                if (lane == 0) p1 = v[(8 - k) & 7];
                E1[k] = v[k] + p1;
                O1[k] = v[k] - p1;
            }
#pragma unroll
            for (int k = 0; k < 2; k++) {
                int c = lane + 32 * k;
                float qe = __shfl_sync(0xFFFFFFFFu, E1[3 - k], sp);
                float qo = __shfl_sync(0xFFFFFFFFu, O1[3 - k], sp);
                if (k == 1 && lane == 0) { qe = E1[3]; qo = O1[3]; }
                float ep = E1[k] + qe, em = E1[k] - qe;
                float op = O1[k] + qo, om = O1[k] - qo;
                if (c >= 1 && c <= 63) {
                    sEp[c * 130 + slot] = __float2half_rn(ep);
                    sEm[c * 130 + slot] = __float2half_rn(em);
                    sOp[c * 130 + slot] = __float2half_rn(op);
                    sOm[c * 130 + slot] = __float2half_rn(om);
                }
            }
            if (lane == 0) {
                sbase[row * 4 + 0] = v[0];
                sbase[row * 4 + 1] = v[4];
                sbase[row * 4 + 2] = v[2] + v[6];
                sbase[row * 4 + 3] = v[2] - v[6];
            }
        }
        __syncwarp();

        int row0 = slot0 + 128 * it;
        float cp[4], cc[4], zp[4], zc[4];
#pragma unroll
        for (int j = 0; j < 4; j++) {
            cp[j] = 1.f;  cc[j] = t1x[j];
            zp[j] = 0.f;  zc[j] = t1y[j];
        }
        float re[4][2], im[4][2];
        {
            const float* b0 = sbase + row0 * 4;
            const float* b1 = sbase + (row0 + 1) * 4;
            float base0 = b0[0] + sgn1 * b0[1] + c64a * b0[2];
            float base1 = b1[0] + sgn1 * b1[1] + c64a * b1[2];
            float imb0 = -s64a * b0[3];
            float imb1 = -s64a * b1[3];
#pragma unroll
            for (int j = 0; j < 4; j++) {
                re[j][0] = base0;  re[j][1] = base1;
                im[j][0] = imb0;   im[j][1] = imb1;
            }
        }
#pragma unroll 7
        for (int s = 1; s < 64; s++) {
            float2 e = __half22float2(*(const __half2*)(EE + s * 130 + slot0));
            float2 o = __half22float2(*(const __half2*)(OO + s * 130 + slot0));
#pragma unroll
            for (int j = 0; j < 4; j++) {
                re[j][0] += e.x * cc[j];  im[j][0] -= o.x * zc[j];
                re[j][1] += e.y * cc[j];  im[j][1] -= o.y * zc[j];
                float cn = Kk[j] * cc[j] - cp[j];  cp[j] = cc[j];  cc[j] = cn;
                float zn = Kk[j] * zc[j] - zp[j];  zp[j] = zc[j];  zc[j] = zn;
            }
        }
        const float SC = 1.f / 256.f;
#pragma unroll
        for (int j = 0; j < 4; j++) {
            int ky = ky0 + 8 * j;
#pragma unroll
            for (int r = 0; r < 2; r++)
                sX1[(row0 + r) * 32 + ky] = make_float2(re[j][r] * SC, im[j][r] * SC);
        }
        __syncwarp();
    }
    __syncthreads();

    // ---- phase 2: 4x fold in x (in place) ----
    for (int e = tid; e < 63 * 32; e += 512) {
        int xx = (e >> 5) + 1, ky = e & 31;
        float2 a = sX1[xx * 32 + ky];
        float2 b = sX1[(256 - xx) * 32 + ky];
        float2 c = sX1[(128 - xx) * 32 + ky];
        float2 d = sX1[(128 + xx) * 32 + ky];
        sX1[xx * 32 + ky]         = make_float2(a.x + b.x + c.x + d.x, a.y + b.y + c.y + d.y);
        sX1[(256 - xx) * 32 + ky] = make_float2(a.x + b.x - c.x - d.x, a.y + b.y - c.y - d.y);
        sX1[(128 - xx) * 32 + ky] = make_float2(a.x - b.x + c.x - d.x, a.y - b.y + c.y - d.y);
        sX1[(128 + xx) * 32 + ky] = make_float2(a.x - b.x - c.x + d.x, a.y - b.y - c.y + d.y);
    }
    __syncthreads();

    // ---- phase 2: DFT along x (63 terms), 2 freqs per thread ----
    int ky = tid & 31, g = tid >> 5;          // g = 0..15, freqs {g, g+16}
    size_t obase = (size_t)bid * 2016;        // [bi][fk] layout
    int p = g & 1;
    float Cr0=0,Ci0=0,Sr0=0,Si0=0, Cr1=0,Ci1=0,Sr1=0,Si1=0;
#pragma unroll 7
    for (int xx = 1; xx < 64; xx++) {
        int eeIdx = (p ? (256 - xx) : xx) * 32 + ky;
        int ooIdx = (p ? (128 - xx) : (128 + xx)) * 32 + ky;
        float2 e = sX1[eeIdx];
        float2 o = sX1[ooIdx];
        const float2* twr = &g_tw1[(xx - 1) * 32];
        float2 t0 = __ldg(twr + g);
        float2 t1 = __ldg(twr + g + 16);
        Cr0 += e.x*t0.x; Ci0 += e.y*t0.x; Sr0 += o.x*t0.y; Si0 += o.y*t0.y;
        Cr1 += e.x*t1.x; Ci1 += e.y*t1.x; Sr1 += o.x*t1.y; Si1 += o.y*t1.y;
    }
    float2 b0   = sX1[0 * 32 + ky];
    float2 b128 = sX1[128 * 32 + ky];
    float2 x64  = sX1[64 * 32 + ky];
    float2 x192 = sX1[192 * 32 + ky];
    float sgnB = p ? -1.f : 1.f;
    float baseR = b0.x + sgnB * b128.x, baseI = b0.y + sgnB * b128.y;
    float E64r = x64.x + x192.x, E64i = x64.y + x192.y;
    float O64r = x64.x - x192.x, O64i = x64.y - x192.y;
    float tpR, tpI, tmR, tmI;
    int gm4 = g & 3;
    if (!p) {
        float c4 = (gm4 == 0) ? 1.f : -1.f;
        tpR = tmR = c4 * E64r;  tpI = tmI = c4 * E64i;
    } else {
        float s4 = (gm4 == 1) ? 1.f : -1.f;
        tpR = s4 * O64i;  tpI = -s4 * O64r;
        tmR = -s4 * O64i; tmI = s4 * O64r;
    }
#define K2OUT(FQ, CR, CI, SR, SI)                                                        \
    g_X2[obase + (31 + (FQ)) * 32 + ky] =                                                \
        make_float2(baseR + tpR + (CR) + (SI), baseI + tpI + (CI) - (SR));               \
    if ((FQ) > 0)                                                                        \
        g_X2[obase + (31 - (FQ)) * 32 + ky] =                                            \
            make_float2(baseR + tmR + (CR) - (SI), baseI + tmI + (CI) + (SR));
    K2OUT(g,      Cr0, Ci0, Sr0, Si0)
    K2OUT(g + 16, Cr1, Ci1, Sr1, Si1)
#undef K2OUT
}

// ---------------- K3: channel mix, 4 (f,ky) tiles/block, fp16 W (one LDG.128/iter) ---
__global__ __launch_bounds__(256, 4) void sc_k3() {
    __shared__ __align__(16) float2 sX[4 * 1024];   // [tile][bi]; reused as stage
    int tid = threadIdx.x, bid = blockIdx.x;        // bid covers fk0 = bid*4
    int tile = tid >> 6, t = tid & 63;
    int og = t & 15, bg = t >> 4;
    int fk = bid * 4 + tile;
    int fk0 = bid * 4;
    for (int q = tid; q < 1024; q += 256) {         // q = bi
        const float4* src = (const float4*)(g_X2 + (size_t)q * 2016 + fk0);
        float4 a = src[0];                          // fk0+0, fk0+1
        float4 b = src[1];                          // fk0+2, fk0+3
        sX[q]        = make_float2(a.x, a.y);
        sX[1024 + q] = make_float2(a.z, a.w);
        sX[2048 + q] = make_float2(b.x, b.y);
        sX[3072 + q] = make_float2(b.z, b.w);
    }
    __syncthreads();

    float ar[4][4], ai[4][4];
#pragma unroll
    for (int bb = 0; bb < 4; bb++)
#pragma unroll
        for (int oo = 0; oo < 4; oo++) { ar[bb][oo] = 0.f; ai[bb][oo] = 0.f; }

    const __half2* Wbase = g_W + (size_t)fk * 4096 + og * 4;
    const float2* Xbase = sX + tile * 1024 + bg * 4 * 64;
#pragma unroll 4
    for (int i = 0; i < 64; i++) {
        float4 raw = __ldg((const float4*)(Wbase + i * 64));   // 4 complex fp16 weights
        const __half2* hp = (const __half2*)&raw;
        float2 w0 = __half22float2(hp[0]);
        float2 w1 = __half22float2(hp[1]);
        float2 w2 = __half22float2(hp[2]);
        float2 w3 = __half22float2(hp[3]);
        float2 v0 = Xbase[i];
        float2 v1 = Xbase[64 + i];
        float2 v2 = Xbase[128 + i];
        float2 v3 = Xbase[192 + i];
#define CMAC(BB, V)                                                          \
        ar[BB][0] += V.x*w0.x - V.y*w0.y;  ai[BB][0] += V.x*w0.y + V.y*w0.x; \
        ar[BB][1] += V.x*w1.x - V.y*w1.y;  ai[BB][1] += V.x*w1.y + V.y*w1.x; \
        ar[BB][2] += V.x*w2.x - V.y*w2.y;  ai[BB][2] += V.x*w2.y + V.y*w2.x; \
        ar[BB][3] += V.x*w3.x - V.y*w3.y;  ai[BB][3] += V.x*w3.y + V.y*w3.x;
        CMAC(0, v0) CMAC(1, v1) CMAC(2, v2) CMAC(3, v3)
#undef CMAC
    }
    __syncthreads();
#pragma unroll
    for (int bb = 0; bb < 4; bb++)
#pragma unroll
        for (int oo = 0; oo < 4; oo++) {
            int bo = (bg * 4 + bb) * 64 + og * 4 + oo;
            sX[bo * 4 + tile] = make_float2(ar[bb][oo], ai[bb][oo]);
        }
    __syncthreads();
    for (int q = tid; q < 2048; q += 256) {
        int bo = q >> 1, half = q & 1;
        float4 val = *(const float4*)(sX + bo * 4 + half * 2);
        *(float4*)(g_X3 + (size_t)bo * 2016 + fk0 + half * 2) = val;
    }
}

// ---------------- K45: fused iDFT-x + irfft-y per (b,o); 8 rows/thread phase 2 -------
#define SMEM45 ((8192 + 2016 + 992 + 992 + 264) * 8)
__global__ __launch_bounds__(256, 2) void sc_k45(float* __restrict__ out) {
    extern __shared__ float smf[];
    float2* sYt  = (float2*)smf;            // [x(256)][ky(32)]
    float2* sX3  = sYt + 8192;              // 2016
    float2* sU   = sX3 + 2016;              // 992
    float2* sV   = sU + 992;                // 992
    float2* stab = sV + 992;                // 264
    int tid = threadIdx.x, bid = blockIdx.x;            // bid = b*64+o

    // ---- phase 1: iDFT along x -> sYt ----
    {
        const float4* src = (const float4*)(g_X3 + (size_t)bid * 2016);
        float4* dst = (float4*)sX3;
        for (int q = tid; q < 1008; q += 256) dst[q] = src[q];
        for (int q = tid; q < 264; q += 256) stab[q] = g_tab[q];
    }
    __syncthreads();
    for (int e = tid; e < 992; e += 256) {
        int ky = e & 31, fq = (e >> 5) + 1;
        float2 P = sX3[(31 + fq) * 32 + ky];
        float2 Q = sX3[(31 - fq) * 32 + ky];
        sU[e] = make_float2(P.x + Q.x, P.y + Q.y);
        sV[e] = make_float2(-(P.y - Q.y), P.x - Q.x);   // i*(P-Q)
    }
    __syncthreads();

    {
        int ky4 = (tid & 7) * 4, xs = tid >> 3;
        const float4* m = (const float4*)(sX3 + 31 * 32 + ky4);
        float4 m01 = m[0], m23 = m[1];
        for (int xi = 0; xi < 4; xi++) {
            int xx = xs + 32 * xi;
            float c0 = m01.x, c1 = m01.y, c2 = m01.z, c3 = m01.w;
            float c4 = m23.x, c5 = m23.y, c6 = m23.z, c7 = m23.w;
            float s0 = 0, s1 = 0, s2 = 0, s3 = 0, s4 = 0, s5 = 0, s6 = 0, s7 = 0;
            int p = 0;
#pragma unroll 4
            for (int fq = 1; fq < 32; fq++) {
                p = (p + xx) & 255;
                float2 t = stab[tp(p)];
                const float4* up = (const float4*)(sU + (fq - 1) * 32 + ky4);
                const float4* vp = (const float4*)(sV + (fq - 1) * 32 + ky4);
                float4 u01 = up[0], u23 = up[1], v01 = vp[0], v23 = vp[1];
                c0 += t.x * u01.x;  s0 += t.y * v01.x;
                c1 += t.x * u01.y;  s1 += t.y * v01.y;
                c2 += t.x * u01.z;  s2 += t.y * v01.z;
                c3 += t.x * u01.w;  s3 += t.y * v01.w;
                c4 += t.x * u23.x;  s4 += t.y * v23.x;
                c5 += t.x * u23.y;  s5 += t.y * v23.y;
                c6 += t.x * u23.z;  s6 += t.y * v23.z;
                c7 += t.x * u23.w;  s7 += t.y * v23.w;
            }
            float4* o1 = (float4*)(sYt + xx * 32 + ky4);
            o1[0] = make_float4(c0 + s0, c1 + s1, c2 + s2, c3 + s3);
            o1[1] = make_float4(c4 + s4, c5 + s5, c6 + s6, c7 + s7);
            if (xx > 0) {
                float4* o2 = (float4*)(sYt + (256 - xx) * 32 + ky4);
                o2[0] = make_float4(c0 - s0, c1 - s1, c2 - s2, c3 - s3);
                o2[1] = make_float4(c4 - s4, c5 - s5, c6 - s6, c7 - s7);
            }
        }
        if (tid < 32) {
            int ky = tid;
            float2 acc = sX3[31 * 32 + ky];
#pragma unroll 4
            for (int fq = 1; fq < 32; fq++) {
                float2 u = sU[(fq - 1) * 32 + ky];
                float sg = (fq & 1) ? -1.f : 1.f;
                acc.x += sg * u.x;  acc.y += sg * u.y;
            }
            sYt[128 * 32 + ky] = acc;
        }
    }
    __syncthreads();

    // ---- phase 2: irfft along y, 8 rows/thread, 4 outer iterations ----
    int l = tid & 31, w = tid >> 5;
    float2 tA = __ldg(&g_tw1[l]);
    const float R45 = 0.70710678118654752f;
    float cB1 = (tA.x - tA.y) * R45;
    float sB1 = (tA.x + tA.y) * R45;
    float KA = 2.f * tA.x, KB = 2.f * cB1;
    const float SC1 = 1.f / 256.f, SC2 = 2.f / 256.f;

    for (int rgh = 0; rgh < 4; rgh++) {
        const float2* sY = sYt + (rgh * 64 + w * 8) * 32;   // 8 rows for this thread
        float cAc = 1.f, cAp = tA.x;
        float zAc = 0.f, zAp = -tA.y;
        float cBc = 1.f, cBp = cB1;
        float zBc = 0.f, zBp = -sB1;

        float Ae0[8]={0,0,0,0,0,0,0,0}, Se0[8]={0,0,0,0,0,0,0,0};
        float Ao0[8]={0,0,0,0,0,0,0,0}, So0[8]={0,0,0,0,0,0,0,0};
        float Ae1[8]={0,0,0,0,0,0,0,0}, Se1[8]={0,0,0,0,0,0,0,0};
        float Ao1[8]={0,0,0,0,0,0,0,0}, So1[8]={0,0,0,0,0,0,0,0};

#pragma unroll 4
        for (int kp = 0; kp < 16; kp++) {
            float n;
            n = KA * cAc - cAp;  cAp = cAc;  cAc = n;
            n = KA * zAc - zAp;  zAp = zAc;  zAc = n;
            n = KB * cBc - cBp;  cBp = cBc;  cBc = n;
            n = KB * zBc - zBp;  zBp = zBc;  zBc = n;
            int kyo = 2 * kp + 1;
#pragma unroll
            for (int r = 0; r < 8; r++) {
                float2 v = sY[r * 32 + kyo];
                Ao0[r] += v.x * cAc;  So0[r] += v.y * zAc;
                Ao1[r] += v.x * cBc;  So1[r] += v.y * zBc;
            }
            if (kp < 15) {
                n = KA * cAc - cAp;  cAp = cAc;  cAc = n;
                n = KA * zAc - zAp;  zAp = zAc;  zAc = n;
                n = KB * cBc - cBp;  cBp = cBc;  cBc = n;
                n = KB * zBc - zBp;  zBp = zBc;  zBc = n;
                int kye = 2 * kp + 2;
#pragma unroll
                for (int r = 0; r < 8; r++) {
                    float2 v = sY[r * 32 + kye];
                    Ae0[r] += v.x * cAc;  Se0[r] += v.y * zAc;
                    Ae1[r] += v.x * cBc;  Se1[r] += v.y * zBc;
                }
            }
        }

#pragma unroll
        for (int r = 0; r < 8; r++) {
            size_t ob = ((size_t)bid * 256 + rgh * 64 + w * 8 + r) * 256;
            float bx = sY[r * 32].x * SC1;
            float a  = SC2 * (Ae0[r] + Ao0[r]) + bx;
            float s  = SC2 * (Se0[r] + So0[r]);
            float am = SC2 * (Ae0[r] - Ao0[r]) + bx;
            float sm = SC2 * (Se0[r] - So0[r]);
            out[ob + l]       = a - s;
            out[ob + 128 - l] = am + sm;
            if (l > 0) {
                out[ob + 256 - l] = a + s;
                out[ob + 128 + l] = am - sm;
            }
            float a1  = SC2 * (Ae1[r] + Ao1[r]) + bx;
            float s1  = SC2 * (Se1[r] + So1[r]);
            float am1 = SC2 * (Ae1[r] - Ao1[r]) + bx;
            float sm1 = SC2 * (Se1[r] - So1[r]);
            out[ob + 32 + l]  = a1 - s1;
            out[ob + 224 - l] = a1 + s1;
            out[ob + 96 - l]  = am1 + sm1;
            out[ob + 160 + l] = am1 - sm1;
        }
        // tail t = 64 / 192 for these 8 rows
        {
            int ky = l;
            float sc = (ky == 0) ? SC1 : SC2;
            int m4 = ky & 3;
            float c64 = (m4 == 0) ? sc : (m4 == 2 ? -sc : 0.f);
            float s64 = (m4 == 1) ? sc : (m4 == 3 ? -sc : 0.f);
#pragma unroll
            for (int r = 0; r < 8; r++) {
                float2 v = sY[r * 32 + ky];
                float p = v.x * c64 - v.y * s64;
                float q = v.x * c64 + v.y * s64;
#pragma unroll
                for (int off = 16; off; off >>= 1) {
                    p += __shfl_xor_sync(0xFFFFFFFFu, p, off);
                    q += __shfl_xor_sync(0xFFFFFFFFu, q, off);
                }
                if (l == 0) {
                    size_t ob = ((size_t)bid * 256 + rgh * 64 + w * 8 + r) * 256;
                    out[ob + 64]  = p;
                    out[ob + 192] = q;
                }
            }
        }
    }
}

// ---------------- launch: fork W-build onto a side stream, overlap with K12 ----------
extern "C" void kernel_launch(void* const* d_in, const int* in_sizes, int n_in,
                              void* d_out, int out_size) {
    const float* x   = (const float*)d_in[0];
    const float* y0r = (const float*)d_in[1];
    const float* y0i = (const float*)d_in[2];
    const float* ypr = (const float*)d_in[3];
    const float* ypi = (const float*)d_in[4];
    const float* w00 = (const float*)d_in[5];
    float* out = (float*)d_out;

    cudaFuncSetAttribute(sc_k12, cudaFuncAttributeMaxDynamicSharedMemorySize, SMEM12);
    cudaFuncSetAttribute(sc_k45, cudaFuncAttributeMaxDynamicSharedMemorySize, SMEM45);

    cudaStream_t s2;
    cudaEvent_t evF, evJ;
    cudaStreamCreateWithFlags(&s2, cudaStreamNonBlocking);
    cudaEventCreateWithFlags(&evF, cudaEventDisableTiming);
    cudaEventCreateWithFlags(&evJ, cudaEventDisableTiming);

    // fork: side stream joins the capture graph at the root
    cudaEventRecord(evF, 0);
    cudaStreamWaitEvent(s2, evF, 0);

    // side stream: W build (feeds only K3)
    sc_build_w0<<<(63 * 4096 + 255) / 256, 256, 0, s2>>>(y0r, y0i, w00);
    sc_build_wt<<<dim3(62, 128), dim3(32, 8), 0, s2>>>(ypr, ypi);
    cudaEventRecord(evJ, s2);

    // main stream: tables -> K12
    sc_tabs<<<9, 256>>>();
    sc_k12<<<1024, 512, SMEM12>>>(x);

    // join before K3 (needs g_W and g_X2)
    cudaStreamWaitEvent(0, evJ, 0);
    sc_k3<<<504, 256>>>();
    sc_k45<<<1024, 256, SMEM45>>>(out);
}